// round 14
// baseline (speedup 1.0000x reference)
#include <cuda_runtime.h>
#include <cuda_fp16.h>
#include <math.h>
#include <stdint.h>

#define MAXN 100000
#define MAXE 131072

// ---------------- scratch (device globals; no allocation allowed) ----------------
__device__ __align__(128) float  g_ZXT[256 * 384];
__device__ __align__(128) __half g_XIJ[(size_t)MAXE * 768];
__device__ __align__(128) __half g_U[(size_t)2 * MAXE * 768];   // U1 | U2
__device__ __align__(128) __half g_XZX[(size_t)MAXE * 768];

// fp16 planes
__device__ __align__(128) __half g_xh [(size_t)MAXN * 256];
__device__ __align__(128) __half g_Zc [(size_t)MAXN * 384];
__device__ __align__(128) __half g_Ph [(size_t)MAXE * 256];
__device__ __align__(128) __half g_ZZh[(size_t)MAXE * 384];
__device__ __align__(128) __half g_Gh [(size_t)2 * MAXE * 256]; // G1|G2
__device__ __align__(128) __half g_Th [(size_t)MAXE * 256];
// weights, single fp16 plane
__device__ __align__(128) __half g_W1 [256 * 256];
__device__ __align__(128) __half g_W2 [768 * 256];
__device__ __align__(128) __half g_ZW2[768 * 256];
__device__ __align__(128) __half g_ZXW[768 * 256];
__device__ __align__(128) __half g_ZXTq[256 * 384];

__device__ __forceinline__ float silu_f(float v) { return v / (1.0f + __expf(-v)); }

__device__ __forceinline__ uint32_t smem_u32(const void* p) {
    uint32_t a;
    asm("{ .reg .u64 t; cvta.to.shared.u64 t, %1; cvt.u32.u64 %0, t; }" : "=r"(a) : "l"(p));
    return a;
}

#define CP_ASYNC16(saddr, gptr) \
    asm volatile("cp.async.cg.shared.global [%0], [%1], 16;" :: "r"(saddr), "l"(gptr))
#define CP_COMMIT() asm volatile("cp.async.commit_group;")

__device__ __forceinline__ void ldm_x4(uint32_t addr, uint32_t& r0, uint32_t& r1,
                                       uint32_t& r2, uint32_t& r3) {
    asm volatile("ldmatrix.sync.aligned.m8n8.x4.shared.b16 {%0,%1,%2,%3}, [%4];"
                 : "=r"(r0), "=r"(r1), "=r"(r2), "=r"(r3) : "r"(addr));
}
__device__ __forceinline__ void ldm_x4t(uint32_t addr, uint32_t& r0, uint32_t& r1,
                                        uint32_t& r2, uint32_t& r3) {
    asm volatile("ldmatrix.sync.aligned.m8n8.x4.trans.shared.b16 {%0,%1,%2,%3}, [%4];"
                 : "=r"(r0), "=r"(r1), "=r"(r2), "=r"(r3) : "r"(addr));
}
__device__ __forceinline__ void mma_fp16(float* c, const uint32_t* a, const uint32_t* b) {
    asm volatile(
        "mma.sync.aligned.m16n8k16.row.col.f32.f16.f16.f32 "
        "{%0,%1,%2,%3}, {%4,%5,%6,%7}, {%8,%9}, {%0,%1,%2,%3};"
        : "+f"(c[0]), "+f"(c[1]), "+f"(c[2]), "+f"(c[3])
        : "r"(a[0]), "r"(a[1]), "r"(a[2]), "r"(a[3]), "r"(b[0]), "r"(b[1]));
}

static constexpr int P_PITCH = 528;                 // 256 fp16 + 16B pad
static constexpr int A_PANEL = 128 * P_PITCH;       // 67584
static constexpr int PG_SMEM = 3 * A_PANEL;         // 202752

// ===== Panel GEMM (K=256): A panel resident in SMEM, loop over N col-blocks =====
template <bool SILU>
__global__ __launch_bounds__(256, 1) void gemm_panel(
    const __half* __restrict__ A, const __half* __restrict__ B,
    const float* __restrict__ bias,
    __half* __restrict__ C,
    int M, int N) {
    const int K = 256;
    extern __shared__ char smem[];
    const uint32_t sb = smem_u32(smem);
    const int tid = threadIdx.x, wid = tid >> 5, lane = tid & 31;
    const int row0 = blockIdx.x * 128;
    const int wm = wid & 3, wn = wid >> 2;
    const int NB = N >> 7;

    auto load_A = [&]() {
        #pragma unroll
        for (int it = 0; it < 16; it++) {
            int idx = tid + it * 256;
            int r = idx >> 5, c = idx & 31;
            CP_ASYNC16(sb + r * P_PITCH + c * 16,
                       A + (size_t)(row0 + r) * K + c * 8);
        }
        CP_COMMIT();
    };
    auto load_B = [&](int j) {
        const uint32_t bb = sb + A_PANEL + (j & 1) * A_PANEL;
        const int cb = j * 128;
        #pragma unroll
        for (int it = 0; it < 16; it++) {
            int idx = tid + it * 256;
            int r = idx >> 5, c = idx & 31;
            CP_ASYNC16(bb + r * P_PITCH + c * 16,
                       B + (size_t)(cb + r) * K + c * 8);
        }
        CP_COMMIT();
    };

    load_A();
    load_B(0);
    asm volatile("cp.async.wait_group 0;");
    __syncthreads();

    const int rowA = wm * 32 + (lane & 15);
    const int kparA = (lane >> 4) * 8;
    const int rowB = (lane & 7) + ((lane >> 4) << 3);
    const int kparB = ((lane >> 3) & 1) * 8;
    const int qrow = lane >> 2, qcol = (lane & 3) * 2;

    for (int j = 0; j < NB; j++) {
        if (j + 1 < NB) load_B(j + 1);

        float acc[2][8][4];
        #pragma unroll
        for (int i = 0; i < 2; i++)
            #pragma unroll
            for (int q = 0; q < 8; q++)
                #pragma unroll
                for (int h = 0; h < 4; h++) acc[i][q][h] = 0.0f;

        const uint32_t bb = sb + A_PANEL + (j & 1) * A_PANEL;
        #pragma unroll
        for (int ks = 0; ks < 16; ks++) {
            uint32_t ah[2][4];
            #pragma unroll
            for (int mf = 0; mf < 2; mf++) {
                uint32_t aA = sb + (uint32_t)(rowA + mf * 16) * P_PITCH +
                              (uint32_t)(kparA + ks * 16) * 2;
                ldm_x4(aA, ah[mf][0], ah[mf][1], ah[mf][2], ah[mf][3]);
            }
            #pragma unroll
            for (int nf2 = 0; nf2 < 4; nf2++) {
                uint32_t bh[2][2];
                uint32_t aB = bb + (uint32_t)(wn * 64 + nf2 * 16 + rowB) * P_PITCH +
                              (uint32_t)(kparB + ks * 16) * 2;
                ldm_x4(aB, bh[0][0], bh[0][1], bh[1][0], bh[1][1]);
                #pragma unroll
                for (int mf = 0; mf < 2; mf++)
                    #pragma unroll
                    for (int q = 0; q < 2; q++)
                        mma_fp16(acc[mf][nf2 * 2 + q], ah[mf], bh[q]);
            }
        }

        #pragma unroll
        for (int nf = 0; nf < 8; nf++) {
            const int col = j * 128 + wn * 64 + nf * 8 + qcol;
            float b0 = bias ? bias[col] : 0.0f;
            float b1 = bias ? bias[col + 1] : 0.0f;
            #pragma unroll
            for (int mf = 0; mf < 2; mf++) {
                #pragma unroll
                for (int h = 0; h < 2; h++) {
                    const int row = row0 + wm * 32 + mf * 16 + qrow + h * 8;
                    float v0 = acc[mf][nf][h * 2 + 0] + b0;
                    float v1 = acc[mf][nf][h * 2 + 1] + b1;
                    if (SILU) { v0 = silu_f(v0); v1 = silu_f(v1); }
                    *reinterpret_cast<__half2*>(C + (size_t)row * N + col) =
                        __halves2half2(__float2half(v0), __float2half(v1));
                }
            }
        }

        if (j + 1 < NB) {
            asm volatile("cp.async.wait_group 0;");
            __syncthreads();
        }
    }
}

// ===== Fused H->XIJ: phase1 H=silu(P@W1^T+b1) into SMEM, phase2 XIJ=H@W2^T+b2 =====
// SMEM slots: S0 = P (phase1) / B odd (phase2); S1 = H panel; S2 = B.
__global__ __launch_bounds__(256, 1) void gemm_fused_xij(
    const __half* __restrict__ P,
    const __half* __restrict__ W1, const float* __restrict__ b1,
    const __half* __restrict__ W2, const float* __restrict__ b2,
    __half* __restrict__ XIJ, int M) {
    const int K = 256;
    extern __shared__ char smem[];
    const uint32_t sb = smem_u32(smem);
    const uint32_t S1 = sb + A_PANEL, S2 = sb + 2 * A_PANEL;
    const int tid = threadIdx.x, wid = tid >> 5, lane = tid & 31;
    const int row0 = blockIdx.x * 128;
    const int wm = wid & 3, wn = wid >> 2;

    auto load_panel = [&](uint32_t dst, const __half* src, int rowBase) {
        #pragma unroll
        for (int it = 0; it < 16; it++) {
            int idx = tid + it * 256;
            int r = idx >> 5, c = idx & 31;
            CP_ASYNC16(dst + r * P_PITCH + c * 16,
                       src + (size_t)(rowBase + r) * K + c * 8);
        }
        CP_COMMIT();
    };

    const int rowA = wm * 32 + (lane & 15);
    const int kparA = (lane >> 4) * 8;
    const int rowB = (lane & 7) + ((lane >> 4) << 3);
    const int kparB = ((lane >> 3) & 1) * 8;
    const int qrow = lane >> 2, qcol = (lane & 3) * 2;

    // ---------- phase 1: H panel into S1 ----------
    load_panel(sb, P, row0);
    for (int j1 = 0; j1 < 2; j1++) {
        load_panel(S2, W1, j1 * 128);
        asm volatile("cp.async.wait_group 0;");
        __syncthreads();

        float acc[2][8][4];
        #pragma unroll
        for (int i = 0; i < 2; i++)
            #pragma unroll
            for (int q = 0; q < 8; q++)
                #pragma unroll
                for (int h = 0; h < 4; h++) acc[i][q][h] = 0.0f;

        #pragma unroll
        for (int ks = 0; ks < 16; ks++) {
            uint32_t ah[2][4];
            #pragma unroll
            for (int mf = 0; mf < 2; mf++) {
                uint32_t aA = sb + (uint32_t)(rowA + mf * 16) * P_PITCH +
                              (uint32_t)(kparA + ks * 16) * 2;
                ldm_x4(aA, ah[mf][0], ah[mf][1], ah[mf][2], ah[mf][3]);
            }
            #pragma unroll
            for (int nf2 = 0; nf2 < 4; nf2++) {
                uint32_t bh[2][2];
                uint32_t aB = S2 + (uint32_t)(wn * 64 + nf2 * 16 + rowB) * P_PITCH +
                              (uint32_t)(kparB + ks * 16) * 2;
                ldm_x4(aB, bh[0][0], bh[0][1], bh[1][0], bh[1][1]);
                #pragma unroll
                for (int mf = 0; mf < 2; mf++)
                    #pragma unroll
                    for (int q = 0; q < 2; q++)
                        mma_fp16(acc[mf][nf2 * 2 + q], ah[mf], bh[q]);
            }
        }

        // silu + bias -> H panel (SMEM, K-major pitch 528)
        #pragma unroll
        for (int nf = 0; nf < 8; nf++) {
            const int col = j1 * 128 + wn * 64 + nf * 8 + qcol;
            float v_b0 = b1[col], v_b1 = b1[col + 1];
            #pragma unroll
            for (int mf = 0; mf < 2; mf++) {
                #pragma unroll
                for (int h = 0; h < 2; h++) {
                    const int rl = wm * 32 + mf * 16 + qrow + h * 8;
                    float v0 = silu_f(acc[mf][nf][h * 2 + 0] + v_b0);
                    float v1 = silu_f(acc[mf][nf][h * 2 + 1] + v_b1);
                    *reinterpret_cast<__half2*>(smem + (S1 - sb) + rl * P_PITCH + col * 2) =
                        __halves2half2(__float2half(v0), __float2half(v1));
                }
            }
        }
        __syncthreads();   // S2 free for next load; H writes visible
    }

    // ---------- phase 2: XIJ = H @ W2^T + b2, 6 col-blocks, double-buffered ----------
    load_panel(S2, W2, 0);      // j=0 -> S2
    load_panel(sb, W2, 128);    // j=1 -> S0 (P dead)

    for (int j = 0; j < 6; j++) {
        if (j + 1 < 6) {
            asm volatile("cp.async.wait_group 1;");
        } else {
            asm volatile("cp.async.wait_group 0;");
        }
        __syncthreads();

        const uint32_t bb = (j & 1) ? sb : S2;

        float acc[2][8][4];
        #pragma unroll
        for (int i = 0; i < 2; i++)
            #pragma unroll
            for (int q = 0; q < 8; q++)
                #pragma unroll
                for (int h = 0; h < 4; h++) acc[i][q][h] = 0.0f;

        #pragma unroll
        for (int ks = 0; ks < 16; ks++) {
            uint32_t ah[2][4];
            #pragma unroll
            for (int mf = 0; mf < 2; mf++) {
                uint32_t aA = S1 + (uint32_t)(rowA + mf * 16) * P_PITCH +
                              (uint32_t)(kparA + ks * 16) * 2;
                ldm_x4(aA, ah[mf][0], ah[mf][1], ah[mf][2], ah[mf][3]);
            }
            #pragma unroll
            for (int nf2 = 0; nf2 < 4; nf2++) {
                uint32_t bh[2][2];
                uint32_t aB = bb + (uint32_t)(wn * 64 + nf2 * 16 + rowB) * P_PITCH +
                              (uint32_t)(kparB + ks * 16) * 2;
                ldm_x4(aB, bh[0][0], bh[0][1], bh[1][0], bh[1][1]);
                #pragma unroll
                for (int mf = 0; mf < 2; mf++)
                    #pragma unroll
                    for (int q = 0; q < 2; q++)
                        mma_fp16(acc[mf][nf2 * 2 + q], ah[mf], bh[q]);
            }
        }
        __syncthreads();                   // all reads of buf(j) done
        if (j + 2 < 6) load_panel(bb, W2, (j + 2) * 128);

        #pragma unroll
        for (int nf = 0; nf < 8; nf++) {
            const int col = j * 128 + wn * 64 + nf * 8 + qcol;
            float v_b0 = b2[col], v_b1 = b2[col + 1];
            #pragma unroll
            for (int mf = 0; mf < 2; mf++) {
                #pragma unroll
                for (int h = 0; h < 2; h++) {
                    const int row = row0 + wm * 32 + mf * 16 + qrow + h * 8;
                    float v0 = acc[mf][nf][h * 2 + 0] + v_b0;
                    float v1 = acc[mf][nf][h * 2 + 1] + v_b1;
                    *reinterpret_cast<__half2*>(XIJ + (size_t)row * 768 + col) =
                        __halves2half2(__float2half(v0), __float2half(v1));
                }
            }
        }
    }
}

// ===== streaming HMMA GEMM for T (K=384) =====
static constexpr int OFF_B = 20480;
static constexpr int BUF   = 30720;
static constexpr int GEMM_SMEM = 3 * BUF;

__global__ __launch_bounds__(256, 1) void gemm_mma_t(
    const __half* __restrict__ A, const __half* __restrict__ B,
    __half* __restrict__ C,
    int M, int N, int K) {
    extern __shared__ char smem[];
    const uint32_t sb = smem_u32(smem);
    const int tid = threadIdx.x, wid = tid >> 5, lane = tid & 31;
    const int col0 = blockIdx.x * 128;
    const int row0 = blockIdx.y * 256;
    const int wm = wid & 3, wn = wid >> 2;

    const int ldr = tid >> 2, ldc = tid & 3;

    auto load_chunk = [&](int i) {
        const uint32_t bufb = sb + (i % 3) * BUF;
        const int k0 = i * 32;
        #pragma unroll
        for (int g = 0; g < 4; g++) {
            int r = ldr + g * 64;
            CP_ASYNC16(bufb + r * 80 + ldc * 16,
                       A + (size_t)(row0 + r) * K + k0 + ldc * 8);
        }
        #pragma unroll
        for (int g = 0; g < 2; g++) {
            int r = ldr + g * 64;
            CP_ASYNC16(bufb + OFF_B + r * 80 + ldc * 16,
                       B + (size_t)(col0 + r) * K + k0 + ldc * 8);
        }
        CP_COMMIT();
    };

    float acc[4][8][4];
    #pragma unroll
    for (int i = 0; i < 4; i++)
        #pragma unroll
        for (int j = 0; j < 8; j++)
            #pragma unroll
            for (int q = 0; q < 4; q++) acc[i][j][q] = 0.0f;

    const int rowA = wm * 64 + (lane & 15);
    const int kparA = (lane >> 4) * 8;
    const int rowB = wn * 64 + (lane & 7) + ((lane >> 4) << 3);
    const int kparB = ((lane >> 3) & 1) * 8;

    const int nCh = K >> 5;
    load_chunk(0);
    if (nCh > 1) load_chunk(1);

    for (int i = 0; i < nCh; i++) {
        if (i + 1 < nCh) {
            asm volatile("cp.async.wait_group 1;");
        } else {
            asm volatile("cp.async.wait_group 0;");
        }
        __syncthreads();
        if (i + 2 < nCh) load_chunk(i + 2);

        const uint32_t bufb = sb + (i % 3) * BUF;
        #pragma unroll
        for (int ks = 0; ks < 2; ks++) {
            uint32_t ah[4][4];
            #pragma unroll
            for (int mf = 0; mf < 4; mf++) {
                uint32_t addrA = bufb +
                    (uint32_t)(rowA + mf * 16) * 80 + (uint32_t)(kparA + ks * 16) * 2;
                ldm_x4(addrA, ah[mf][0], ah[mf][1], ah[mf][2], ah[mf][3]);
            }
            #pragma unroll
            for (int nf2 = 0; nf2 < 4; nf2++) {
                uint32_t bh[2][2];
                uint32_t addrB = bufb + OFF_B +
                    (uint32_t)(rowB + nf2 * 16) * 80 + (uint32_t)(kparB + ks * 16) * 2;
                ldm_x4(addrB, bh[0][0], bh[0][1], bh[1][0], bh[1][1]);
                #pragma unroll
                for (int mf = 0; mf < 4; mf++)
                    #pragma unroll
                    for (int j = 0; j < 2; j++)
                        mma_fp16(acc[mf][nf2 * 2 + j], ah[mf], bh[j]);
            }
        }
    }

    const int qrow = lane >> 2, qcol = (lane & 3) * 2;
    #pragma unroll
    for (int nf = 0; nf < 8; nf++) {
        const int col = col0 + wn * 64 + nf * 8 + qcol;
        #pragma unroll
        for (int mf = 0; mf < 4; mf++) {
            #pragma unroll
            for (int h = 0; h < 2; h++) {
                const int row = row0 + wm * 64 + mf * 16 + qrow + h * 8;
                float v0 = acc[mf][nf][h * 2 + 0];
                float v1 = acc[mf][nf][h * 2 + 1];
                *reinterpret_cast<__half2*>(C + (size_t)row * N + col) =
                    __halves2half2(__float2half(v0), __float2half(v1));
            }
        }
    }
}

// ============ HMMA split-K TN GEMM (1-pass) ==========
static constexpr int TK_PITCH = 272;
static constexpr int TK_PLANE = 32 * TK_PITCH;
static constexpr int TK_BUF   = 2 * TK_PLANE;
static constexpr int TK_SMEM  = 2 * TK_BUF;

__global__ __launch_bounds__(256, 1) void gemm_tn_mma(
    const __half* __restrict__ Ah, const __half* __restrict__ B,
    float* __restrict__ C, int Mc, int Nc, int Ktot, int kChunk, float scale) {
    extern __shared__ char smem[];
    const uint32_t sb = smem_u32(smem);
    const int tid = threadIdx.x, wid = tid >> 5, lane = tid & 31;
    const int col0 = blockIdx.x * 128;
    const int row0 = blockIdx.y * 128;
    const int n0 = blockIdx.z * kChunk;
    const int nEnd = min(n0 + kChunk, Ktot);
    const int wm = wid >> 2, wn = wid & 3;

    const __half* planes[2] = { Ah, B };
    const int baseCol[2] = { row0, col0 };
    const int strideK[2] = { Mc, Nc };

    const int lr0 = tid >> 4, lc0 = tid & 15;
    const int lr1 = lr0 + 16;

    auto load_chunk = [&](int i, int k0) {
        const uint32_t bufb = sb + (i & 1) * TK_BUF;
        #pragma unroll
        for (int p = 0; p < 2; p++) {
            const __half* src = planes[p];
            #pragma unroll
            for (int rep = 0; rep < 2; rep++) {
                int r = rep ? lr1 : lr0;
                int node = k0 + r;
                uint32_t sa = bufb + p * TK_PLANE + r * TK_PITCH + lc0 * 16;
                if (node < nEnd) {
                    CP_ASYNC16(sa, src + (size_t)node * strideK[p] + baseCol[p] + lc0 * 8);
                } else {
                    *reinterpret_cast<uint4*>(smem + (sa - sb)) = make_uint4(0, 0, 0, 0);
                }
            }
        }
        CP_COMMIT();
    };

    float acc[4][4][4];
    #pragma unroll
    for (int i = 0; i < 4; i++)
        #pragma unroll
        for (int j = 0; j < 4; j++)
            #pragma unroll
            for (int q = 0; q < 4; q++) acc[i][j][q] = 0.0f;

    const int krA = (lane & 7) + ((lane >> 4) << 3);
    const int mcA = ((lane >> 3) & 1) * 8;
    const int krB = (lane & 7) + (((lane >> 3) & 1) << 3);
    const int ncB = (lane >> 4) * 8;

    const int nCh = (nEnd - n0 + 31) >> 5;
    load_chunk(0, n0);

    for (int i = 0; i < nCh; i++) {
        const int k0 = n0 + i * 32;
        if (i + 1 < nCh) {
            load_chunk(i + 1, k0 + 32);
            asm volatile("cp.async.wait_group 1;");
        } else {
            asm volatile("cp.async.wait_group 0;");
        }
        __syncthreads();

        const uint32_t bufb = sb + (i & 1) * TK_BUF;
        #pragma unroll
        for (int ks = 0; ks < 2; ks++) {
            uint32_t bh[4][2];
            #pragma unroll
            for (int nf2 = 0; nf2 < 2; nf2++) {
                uint32_t aH = bufb + TK_PLANE +
                    (uint32_t)(krB + ks * 16) * TK_PITCH +
                    (uint32_t)(wn * 32 + nf2 * 16 + ncB) * 2;
                ldm_x4t(aH, bh[nf2 * 2][0], bh[nf2 * 2][1],
                            bh[nf2 * 2 + 1][0], bh[nf2 * 2 + 1][1]);
            }
            uint32_t ah[4][4];
            #pragma unroll
            for (int mf = 0; mf < 4; mf++) {
                uint32_t aH = bufb +
                    (uint32_t)(krA + ks * 16) * TK_PITCH +
                    (uint32_t)(wm * 64 + mf * 16 + mcA) * 2;
                ldm_x4t(aH, ah[mf][0], ah[mf][1], ah[mf][2], ah[mf][3]);
            }
            #pragma unroll
            for (int mf = 0; mf < 4; mf++)
                #pragma unroll
                for (int nf = 0; nf < 4; nf++)
                    mma_fp16(acc[mf][nf], ah[mf], bh[nf]);
        }
        __syncthreads();
    }

    const int qrow = lane >> 2, qcol = (lane & 3) * 2;
    #pragma unroll
    for (int mf = 0; mf < 4; mf++) {
        #pragma unroll
        for (int nf = 0; nf < 4; nf++) {
            #pragma unroll
            for (int h = 0; h < 2; h++) {
                const int row = row0 + wm * 64 + mf * 16 + qrow + h * 8;
                const int col = col0 + wn * 32 + nf * 8 + qcol;
                atomicAdd(&C[(size_t)row * Nc + col], acc[mf][nf][h * 2 + 0] * scale);
                atomicAdd(&C[(size_t)row * Nc + col + 1], acc[mf][nf][h * 2 + 1] * scale);
            }
        }
    }
}

// ---------------- fp32 -> fp16 converts (4 weights merged) ----------------
__global__ void convert4_kernel(
    const float* __restrict__ s0, __half* __restrict__ d0, int n0,
    const float* __restrict__ s1, __half* __restrict__ d1, int n1,
    const float* __restrict__ s2, __half* __restrict__ d2, int n2,
    const float* __restrict__ s3, __half* __restrict__ d3, int n3) {
    int i = blockIdx.x * 256 + threadIdx.x;
    if (i < n0) d0[i] = __float2half(s0[i]);
    i -= n0;
    if (i >= 0 && i < n1) d1[i] = __float2half(s1[i]);
    i -= n1;
    if (i >= 0 && i < n2) d2[i] = __float2half(s2[i]);
    i -= n2;
    if (i >= 0 && i < n3) d3[i] = __float2half(s3[i]);
}

__global__ void convert_kernel(const float* __restrict__ src,
                               __half* __restrict__ dst, int n) {
    int i = blockIdx.x * 256 + threadIdx.x;
    if (i < n) dst[i] = __float2half(src[i]);
}

// ---------------- K0: Zc ----------------
__global__ void zc_kernel(const float* __restrict__ Z,
                          const float* __restrict__ zcw,
                          const float* __restrict__ zcb,
                          __half* __restrict__ Zc, int NL) {
    int idx = blockIdx.x * 256 + threadIdx.x;
    if (idx >= NL) return;
    int n = idx >> 7, l = idx & 127;
    size_t base = (size_t)n * 384 + l;
    float z0 = Z[base], z1 = Z[base + 128], z2 = Z[base + 256];
    #pragma unroll
    for (int c = 0; c < 3; c++) {
        float v = zcw[c * 3 + 0] * z0 + zcw[c * 3 + 1] * z1 + zcw[c * 3 + 2] * z2 + zcb[c];
        Zc[base + (size_t)c * 128] = __float2half(v);
    }
}

// ---------------- K2: per-edge prep ----------------
__global__ __launch_bounds__(128) void edge_prep(
    const float* __restrict__ x, const float* __restrict__ Z,
    const int* __restrict__ tar,
    const float* __restrict__ zw1, const float* __restrict__ zb1,
    __half* __restrict__ Ph, __half* __restrict__ ZZh,
    __half* __restrict__ Gh, int E) {
    int e = blockIdx.x;
    int t = threadIdx.x;
    int src = tar[e], dst = tar[E + e];

    __shared__ float sZi[384], sZj[384];
    __shared__ float red[9][4];
    __shared__ float r9[9], rT9[9];

    const float* xs = x + (size_t)src * 256;
    const float* xd = x + (size_t)dst * 256;
    Ph[(size_t)e * 256 + t]       = __float2half(xs[t] * xd[t]);
    Ph[(size_t)e * 256 + t + 128] = __float2half(xs[t + 128] * xd[t + 128]);

    const float* Zi = Z + (size_t)src * 384;
    const float* Zj = Z + (size_t)dst * 384;
    for (int i = t; i < 384; i += 128) { sZi[i] = Zi[i]; sZj[i] = Zj[i]; }
    __syncthreads();

    for (int i = t; i < 384; i += 128)
        ZZh[(size_t)e * 384 + i] = __float2half(sZi[i] * sZj[i]);

    float loc[9];
    #pragma unroll
    for (int c = 0; c < 3; c++)
        #pragma unroll
        for (int d = 0; d < 3; d++)
            loc[c * 3 + d] = sZi[c * 128 + t] * sZj[d * 128 + t];
    #pragma unroll
    for (int off = 16; off > 0; off >>= 1)
        #pragma unroll
        for (int q = 0; q < 9; q++)
            loc[q] += __shfl_down_sync(0xffffffffu, loc[q], off);
    int warp = t >> 5, lane = t & 31;
    if (lane == 0)
        #pragma unroll
        for (int q = 0; q < 9; q++) red[q][warp] = loc[q];
    __syncthreads();
    if (t < 9) r9[t] = (red[t][0] + red[t][1] + red[t][2] + red[t][3]) * (1.0f / 128.0f);
    __syncthreads();
    if (t < 9) { int c = t / 3, d = t % 3; rT9[t] = r9[d * 3 + c]; }
    __syncthreads();

    #pragma unroll
    for (int rep = 0; rep < 2; rep++) {
        int o = t + rep * 128;
        const float* w = zw1 + (size_t)o * 9;
        float s1 = zb1[o], s2 = zb1[o];
        #pragma unroll
        for (int q = 0; q < 9; q++) { s1 += r9[q] * w[q]; s2 += rT9[q] * w[q]; }
        Gh[(size_t)e * 256 + o]       = __float2half(silu_f(s1));
        Gh[(size_t)(E + e) * 256 + o] = __float2half(silu_f(s2));
    }
}

// ---------------- K4: 4 LayerNorms + product + final dot ----------------
__global__ __launch_bounds__(256) void final_kernel(
    const __half* __restrict__ XIJ, const __half* __restrict__ U,
    const __half* __restrict__ XZX,
    const float* __restrict__ xg, const float* __restrict__ xb,
    const float* __restrict__ zg, const float* __restrict__ zb,
    const float* __restrict__ zxg, const float* __restrict__ zxb,
    const float* __restrict__ lw, const float* __restrict__ lb,
    float* __restrict__ out, int E) {
    int e = blockIdx.x;
    int t = threadIdx.x;
    const __half2* pxij = reinterpret_cast<const __half2*>(XIJ + (size_t)e * 768);
    const __half2* pu1  = reinterpret_cast<const __half2*>(U   + (size_t)e * 768);
    const __half2* pu2  = reinterpret_cast<const __half2*>(U   + (size_t)(E + e) * 768);
    const __half2* pxzx = reinterpret_cast<const __half2*>(XZX + (size_t)e * 768);

    __shared__ float red[8][8];
    __shared__ float stats[8];
    __shared__ float dred[8];

    float v0[4], v1[4], v2[4], v3[4];
    float s[8];
    #pragma unroll
    for (int q = 0; q < 8; q++) s[q] = 0.0f;
    #pragma unroll
    for (int j = 0; j < 2; j++) {
        if (j == 0 || t < 128) {
            int idx = t + j * 256;
            float2 a = __half22float2(pxij[idx]);
            float2 b = __half22float2(pu1[idx]);
            float2 c = __half22float2(pu2[idx]);
            float2 d = __half22float2(pxzx[idx]);
            v0[j*2] = a.x; v0[j*2+1] = a.y;
            v1[j*2] = b.x; v1[j*2+1] = b.y;
            v2[j*2] = c.x; v2[j*2+1] = c.y;
            v3[j*2] = d.x; v3[j*2+1] = d.y;
            s[0] += a.x + a.y; s[1] += a.x*a.x + a.y*a.y;
            s[2] += b.x + b.y; s[3] += b.x*b.x + b.y*b.y;
            s[4] += c.x + c.y; s[5] += c.x*c.x + c.y*c.y;
            s[6] += d.x + d.y; s[7] += d.x*d.x + d.y*d.y;
        }
    }
    #pragma unroll
    for (int off = 16; off > 0; off >>= 1)
        #pragma unroll
        for (int q = 0; q < 8; q++)
            s[q] += __shfl_down_sync(0xffffffffu, s[q], off);
    int warp = t >> 5, lane = t & 31;
    if (lane == 0)
        #pragma unroll
        for (int q = 0; q < 8; q++) red[q][warp] = s[q];
    __syncthreads();
    if (t < 8) {
        float tot = 0.0f;
        #pragma unroll
        for (int w = 0; w < 8; w++) tot += red[t][w];
        stats[t] = tot;
    }
    __syncthreads();

    const float inv = 1.0f / 768.0f;
    const float eps = 1e-5f;
    float m0 = stats[0] * inv, r0 = rsqrtf(stats[1] * inv - m0 * m0 + eps);
    float m1 = stats[2] * inv, r1 = rsqrtf(stats[3] * inv - m1 * m1 + eps);
    float m2 = stats[4] * inv, r2 = rsqrtf(stats[5] * inv - m2 * m2 + eps);
    float m3 = stats[6] * inv, r3 = rsqrtf(stats[7] * inv - m3 * m3 + eps);

    float dot = 0.0f;
    #pragma unroll
    for (int j = 0; j < 2; j++) {
        if (j == 0 || t < 128) {
            int idx = t + j * 256;
            float2 gx  = *reinterpret_cast<const float2*>(xg  + idx * 2);
            float2 bx  = *reinterpret_cast<const float2*>(xb  + idx * 2);
            float2 gz  = *reinterpret_cast<const float2*>(zg  + idx * 2);
            float2 bz  = *reinterpret_cast<const float2*>(zb  + idx * 2);
            float2 gzx = *reinterpret_cast<const float2*>(zxg + idx * 2);
            float2 bzx = *reinterpret_cast<const float2*>(zxb + idx * 2);
            float2 wl  = *reinterpret_cast<const float2*>(lw  + idx * 2);
            #pragma unroll
            for (int h = 0; h < 2; h++) {
                float ga = h ? gx.y : gx.x,  ba = h ? bx.y : bx.x;
                float gb = h ? gz.y : gz.x,  bb = h ? bz.y : bz.x;
                float gc = h ? gzx.y : gzx.x, bc = h ? bzx.y : bzx.x;
                float wv = h ? wl.y : wl.x;
                float a  = (v0[j*2+h] - m0) * r0 * ga + ba;
                float b1 = (v1[j*2+h] - m1) * r1 * gb + bb;
                float b2 = (v2[j*2+h] - m2) * r2 * gb + bb;
                float c  = (v3[j*2+h] - m3) * r3 * gc + bc;
                dot += a * (b1 + b2) * c * wv;
            }
        }
    }
    #pragma unroll
    for (int off = 16; off > 0; off >>= 1)
        dot += __shfl_down_sync(0xffffffffu, dot, off);
    if (lane == 0) dred[warp] = dot;
    __syncthreads();
    if (t == 0) {
        float tot = 0.0f;
        #pragma unroll
        for (int w = 0; w < 8; w++) tot += dred[w];
        out[e] = tot + lb[0];
    }
}

// ---------------- launch ----------------
extern "C" void kernel_launch(void* const* d_in, const int* in_sizes, int n_in,
                              void* d_out, int out_size) {
    const float* x   = (const float*)d_in[0];
    const float* Z   = (const float*)d_in[1];
    const int*   tar = (const int*)  d_in[3];
    const float* xij_w1 = (const float*)d_in[4];
    const float* xij_b1 = (const float*)d_in[5];
    const float* xij_w2 = (const float*)d_in[6];
    const float* xij_b2 = (const float*)d_in[7];
    const float* xij_ln_g = (const float*)d_in[8];
    const float* xij_ln_b = (const float*)d_in[9];
    const float* z_w1 = (const float*)d_in[10];
    const float* z_b1 = (const float*)d_in[11];
    const float* z_w2 = (const float*)d_in[12];
    const float* z_b2 = (const float*)d_in[13];
    const float* z_ln_g = (const float*)d_in[14];
    const float* z_ln_b = (const float*)d_in[15];
    const float* zc_w = (const float*)d_in[16];
    const float* zc_b = (const float*)d_in[17];
    const float* zx_w = (const float*)d_in[18];
    const float* zx_b = (const float*)d_in[19];
    const float* zx_ln_g = (const float*)d_in[20];
    const float* zx_ln_b = (const float*)d_in[21];
    const float* lin_w = (const float*)d_in[22];
    const float* lin_b = (const float*)d_in[23];

    int N = in_sizes[0] / 256;
    int E = in_sizes[3] / 2;
    float zx_coeff = (float)(1.0 / (sqrt((double)N) * 3840.0));

    float* ZXT;
    cudaGetSymbolAddress((void**)&ZXT, g_ZXT);
    __half *XIJ, *U, *XZX;
    cudaGetSymbolAddress((void**)&XIJ, g_XIJ);
    cudaGetSymbolAddress((void**)&U,   g_U);
    cudaGetSymbolAddress((void**)&XZX, g_XZX);

    __half *xh,*Zc,*Ph,*ZZh,*Gh,*Th;
    __half *W1,*W2,*ZW2,*ZXW,*ZXTq;
    cudaGetSymbolAddress((void**)&xh,  g_xh);
    cudaGetSymbolAddress((void**)&Zc,  g_Zc);
    cudaGetSymbolAddress((void**)&Ph,  g_Ph);
    cudaGetSymbolAddress((void**)&ZZh, g_ZZh);
    cudaGetSymbolAddress((void**)&Gh,  g_Gh);
    cudaGetSymbolAddress((void**)&Th,  g_Th);
    cudaGetSymbolAddress((void**)&W1,  g_W1);  cudaGetSymbolAddress((void**)&W2,  g_W2);
    cudaGetSymbolAddress((void**)&ZW2, g_ZW2); cudaGetSymbolAddress((void**)&ZXW, g_ZXW);
    cudaGetSymbolAddress((void**)&ZXTq,g_ZXTq);

    cudaFuncSetAttribute(gemm_panel<true >, cudaFuncAttributeMaxDynamicSharedMemorySize, PG_SMEM);
    cudaFuncSetAttribute(gemm_panel<false>, cudaFuncAttributeMaxDynamicSharedMemorySize, PG_SMEM);
    cudaFuncSetAttribute(gemm_fused_xij, cudaFuncAttributeMaxDynamicSharedMemorySize, PG_SMEM);
    cudaFuncSetAttribute(gemm_mma_t, cudaFuncAttributeMaxDynamicSharedMemorySize, GEMM_SMEM);
    cudaFuncSetAttribute(gemm_tn_mma, cudaFuncAttributeMaxDynamicSharedMemorySize, TK_SMEM);

    // weight converts (merged)
    convert4_kernel<<<(655360 + 255) / 256, 256>>>(
        xij_w1, W1, 65536, xij_w2, W2, 196608,
        z_w2, ZW2, 196608, zx_w, ZXW, 196608);

    // edge prep + biggest GEMM early
    edge_prep<<<E, 128>>>(x, Z, tar, z_w1, z_b1, Ph, ZZh, Gh, E);
    gemm_panel<true ><<<2 * E / 128, 256, PG_SMEM>>>(Gh, ZW2, z_b2, U, 2 * E, 768);

    // zx node path
    int NL = N * 128;
    convert_kernel<<<(N * 256 + 255) / 256, 256>>>(x, xh, N * 256);
    zc_kernel<<<(NL + 255) / 256, 256>>>(Z, zc_w, zc_b, Zc, NL);
    cudaMemsetAsync(ZXT, 0, 256 * 384 * sizeof(float), 0);
    {
        int kChunk = 4000;
        int splits = (N + kChunk - 1) / kChunk;
        dim3 grid(3, 2, splits);
        gemm_tn_mma<<<grid, 256, TK_SMEM>>>(xh, Zc, ZXT, 256, 384, N, kChunk, zx_coeff);
    }
    convert_kernel<<<(98304 + 255) / 256, 256>>>(ZXT, ZXTq, 98304);

    // fused H->XIJ (replaces two kernels + H round-trip)
    gemm_fused_xij<<<E / 128, 256, PG_SMEM>>>(Ph, W1, xij_b1, W2, xij_b2, XIJ, E);

    // T and XZX
    {
        dim3 gT(2, E / 256);
        gemm_mma_t<<<gT, 256, GEMM_SMEM>>>(ZZh, ZXTq, Th, E, 256, 384);
    }
    gemm_panel<false><<<E / 128, 256, PG_SMEM>>>(Th, ZXW, zx_b, XZX, E, 768);

    final_kernel<<<E, 256>>>(XIJ, U, XZX,
                             xij_ln_g, xij_ln_b, z_ln_g, z_ln_b,
                             zx_ln_g, zx_ln_b, lin_w, lin_b,
                             (float*)d_out, E);
}

// round 15
// speedup vs baseline: 1.0183x; 1.0183x over previous
#include <cuda_runtime.h>
#include <cuda_fp16.h>
#include <math.h>
#include <stdint.h>

#define MAXN 100000
#define MAXE 131072

// ---------------- scratch (device globals; no allocation allowed) ----------------
__device__ __align__(128) float  g_ZXT[256 * 384];
__device__ __align__(128) __half g_XIJ[(size_t)MAXE * 768];
__device__ __align__(128) __half g_U[(size_t)2 * MAXE * 768];   // U1 | U2
__device__ __align__(128) __half g_XZX[(size_t)MAXE * 768];

// fp16 planes
__device__ __align__(128) __half g_xh [(size_t)MAXN * 256];
__device__ __align__(128) __half g_Zc [(size_t)MAXN * 384];
__device__ __align__(128) __half g_Ph [(size_t)MAXE * 256];
__device__ __align__(128) __half g_ZZh[(size_t)MAXE * 384];
__device__ __align__(128) __half g_Gh [(size_t)2 * MAXE * 256]; // G1|G2
__device__ __align__(128) __half g_Hh [(size_t)MAXE * 256];
__device__ __align__(128) __half g_Th [(size_t)MAXE * 256];
// weights, single fp16 plane
__device__ __align__(128) __half g_W1 [256 * 256];
__device__ __align__(128) __half g_W2 [768 * 256];
__device__ __align__(128) __half g_ZW2[768 * 256];
__device__ __align__(128) __half g_ZXW[768 * 256];
__device__ __align__(128) __half g_ZXTq[256 * 384];

__device__ __forceinline__ float silu_f(float v) { return v / (1.0f + __expf(-v)); }

__device__ __forceinline__ uint32_t smem_u32(const void* p) {
    uint32_t a;
    asm("{ .reg .u64 t; cvta.to.shared.u64 t, %1; cvt.u32.u64 %0, t; }" : "=r"(a) : "l"(p));
    return a;
}

#define CP_ASYNC16(saddr, gptr) \
    asm volatile("cp.async.cg.shared.global [%0], [%1], 16;" :: "r"(saddr), "l"(gptr))
#define CP_COMMIT() asm volatile("cp.async.commit_group;")

__device__ __forceinline__ void ldm_x4(uint32_t addr, uint32_t& r0, uint32_t& r1,
                                       uint32_t& r2, uint32_t& r3) {
    asm volatile("ldmatrix.sync.aligned.m8n8.x4.shared.b16 {%0,%1,%2,%3}, [%4];"
                 : "=r"(r0), "=r"(r1), "=r"(r2), "=r"(r3) : "r"(addr));
}
__device__ __forceinline__ void ldm_x4t(uint32_t addr, uint32_t& r0, uint32_t& r1,
                                        uint32_t& r2, uint32_t& r3) {
    asm volatile("ldmatrix.sync.aligned.m8n8.x4.trans.shared.b16 {%0,%1,%2,%3}, [%4];"
                 : "=r"(r0), "=r"(r1), "=r"(r2), "=r"(r3) : "r"(addr));
}
__device__ __forceinline__ void mma_fp16(float* c, const uint32_t* a, const uint32_t* b) {
    asm volatile(
        "mma.sync.aligned.m16n8k16.row.col.f32.f16.f16.f32 "
        "{%0,%1,%2,%3}, {%4,%5,%6,%7}, {%8,%9}, {%0,%1,%2,%3};"
        : "+f"(c[0]), "+f"(c[1]), "+f"(c[2]), "+f"(c[3])
        : "r"(a[0]), "r"(a[1]), "r"(a[2]), "r"(a[3]), "r"(b[0]), "r"(b[1]));
}

static constexpr int P_PITCH = 528;                 // 256 fp16 + 16B pad
static constexpr int A_PANEL = 128 * P_PITCH;       // 67584
static constexpr int PG_SMEM = 3 * A_PANEL;         // 202752

// ===== Panel GEMM (K=256): A panel resident in SMEM, loop over N col-blocks =====
template <bool SILU>
__global__ __launch_bounds__(256, 1) void gemm_panel(
    const __half* __restrict__ A, const __half* __restrict__ B,
    const float* __restrict__ bias,
    __half* __restrict__ C,
    int M, int N) {
    const int K = 256;
    extern __shared__ char smem[];
    const uint32_t sb = smem_u32(smem);
    const int tid = threadIdx.x, wid = tid >> 5, lane = tid & 31;
    const int row0 = blockIdx.x * 128;
    const int wm = wid & 3, wn = wid >> 2;
    const int NB = N >> 7;

    auto load_A = [&]() {
        #pragma unroll
        for (int it = 0; it < 16; it++) {
            int idx = tid + it * 256;
            int r = idx >> 5, c = idx & 31;
            CP_ASYNC16(sb + r * P_PITCH + c * 16,
                       A + (size_t)(row0 + r) * K + c * 8);
        }
        CP_COMMIT();
    };
    auto load_B = [&](int j) {
        const uint32_t bb = sb + A_PANEL + (j & 1) * A_PANEL;
        const int cb = j * 128;
        #pragma unroll
        for (int it = 0; it < 16; it++) {
            int idx = tid + it * 256;
            int r = idx >> 5, c = idx & 31;
            CP_ASYNC16(bb + r * P_PITCH + c * 16,
                       B + (size_t)(cb + r) * K + c * 8);
        }
        CP_COMMIT();
    };

    load_A();
    load_B(0);
    asm volatile("cp.async.wait_group 0;");
    __syncthreads();

    const int rowA = wm * 32 + (lane & 15);
    const int kparA = (lane >> 4) * 8;
    const int rowB = (lane & 7) + ((lane >> 4) << 3);
    const int kparB = ((lane >> 3) & 1) * 8;
    const int qrow = lane >> 2, qcol = (lane & 3) * 2;

    for (int j = 0; j < NB; j++) {
        if (j + 1 < NB) load_B(j + 1);

        float acc[2][8][4];
        #pragma unroll
        for (int i = 0; i < 2; i++)
            #pragma unroll
            for (int q = 0; q < 8; q++)
                #pragma unroll
                for (int h = 0; h < 4; h++) acc[i][q][h] = 0.0f;

        const uint32_t bb = sb + A_PANEL + (j & 1) * A_PANEL;
        #pragma unroll
        for (int ks = 0; ks < 16; ks++) {
            uint32_t ah[2][4];
            #pragma unroll
            for (int mf = 0; mf < 2; mf++) {
                uint32_t aA = sb + (uint32_t)(rowA + mf * 16) * P_PITCH +
                              (uint32_t)(kparA + ks * 16) * 2;
                ldm_x4(aA, ah[mf][0], ah[mf][1], ah[mf][2], ah[mf][3]);
            }
            #pragma unroll
            for (int nf2 = 0; nf2 < 4; nf2++) {
                uint32_t bh[2][2];
                uint32_t aB = bb + (uint32_t)(wn * 64 + nf2 * 16 + rowB) * P_PITCH +
                              (uint32_t)(kparB + ks * 16) * 2;
                ldm_x4(aB, bh[0][0], bh[0][1], bh[1][0], bh[1][1]);
                #pragma unroll
                for (int mf = 0; mf < 2; mf++)
                    #pragma unroll
                    for (int q = 0; q < 2; q++)
                        mma_fp16(acc[mf][nf2 * 2 + q], ah[mf], bh[q]);
            }
        }

        #pragma unroll
        for (int nf = 0; nf < 8; nf++) {
            const int col = j * 128 + wn * 64 + nf * 8 + qcol;
            float b0 = bias ? bias[col] : 0.0f;
            float b1 = bias ? bias[col + 1] : 0.0f;
            #pragma unroll
            for (int mf = 0; mf < 2; mf++) {
                #pragma unroll
                for (int h = 0; h < 2; h++) {
                    const int row = row0 + wm * 32 + mf * 16 + qrow + h * 8;
                    float v0 = acc[mf][nf][h * 2 + 0] + b0;
                    float v1 = acc[mf][nf][h * 2 + 1] + b1;
                    if (SILU) { v0 = silu_f(v0); v1 = silu_f(v1); }
                    *reinterpret_cast<__half2*>(C + (size_t)row * N + col) =
                        __halves2half2(__float2half(v0), __float2half(v1));
                }
            }
        }

        if (j + 1 < NB) {
            asm volatile("cp.async.wait_group 0;");
            __syncthreads();
        }
    }
}

// ===== streaming HMMA GEMM for T (K=384) =====
static constexpr int OFF_B = 20480;
static constexpr int BUF   = 30720;
static constexpr int GEMM_SMEM = 3 * BUF;

__global__ __launch_bounds__(256, 1) void gemm_mma_t(
    const __half* __restrict__ A, const __half* __restrict__ B,
    __half* __restrict__ C,
    int M, int N, int K) {
    extern __shared__ char smem[];
    const uint32_t sb = smem_u32(smem);
    const int tid = threadIdx.x, wid = tid >> 5, lane = tid & 31;
    const int col0 = blockIdx.x * 128;
    const int row0 = blockIdx.y * 256;
    const int wm = wid & 3, wn = wid >> 2;

    const int ldr = tid >> 2, ldc = tid & 3;

    auto load_chunk = [&](int i) {
        const uint32_t bufb = sb + (i % 3) * BUF;
        const int k0 = i * 32;
        #pragma unroll
        for (int g = 0; g < 4; g++) {
            int r = ldr + g * 64;
            CP_ASYNC16(bufb + r * 80 + ldc * 16,
                       A + (size_t)(row0 + r) * K + k0 + ldc * 8);
        }
        #pragma unroll
        for (int g = 0; g < 2; g++) {
            int r = ldr + g * 64;
            CP_ASYNC16(bufb + OFF_B + r * 80 + ldc * 16,
                       B + (size_t)(col0 + r) * K + k0 + ldc * 8);
        }
        CP_COMMIT();
    };

    float acc[4][8][4];
    #pragma unroll
    for (int i = 0; i < 4; i++)
        #pragma unroll
        for (int j = 0; j < 8; j++)
            #pragma unroll
            for (int q = 0; q < 4; q++) acc[i][j][q] = 0.0f;

    const int rowA = wm * 64 + (lane & 15);
    const int kparA = (lane >> 4) * 8;
    const int rowB = wn * 64 + (lane & 7) + ((lane >> 4) << 3);
    const int kparB = ((lane >> 3) & 1) * 8;

    const int nCh = K >> 5;
    load_chunk(0);
    if (nCh > 1) load_chunk(1);

    for (int i = 0; i < nCh; i++) {
        if (i + 1 < nCh) {
            asm volatile("cp.async.wait_group 1;");
        } else {
            asm volatile("cp.async.wait_group 0;");
        }
        __syncthreads();
        if (i + 2 < nCh) load_chunk(i + 2);

        const uint32_t bufb = sb + (i % 3) * BUF;
        #pragma unroll
        for (int ks = 0; ks < 2; ks++) {
            uint32_t ah[4][4];
            #pragma unroll
            for (int mf = 0; mf < 4; mf++) {
                uint32_t addrA = bufb +
                    (uint32_t)(rowA + mf * 16) * 80 + (uint32_t)(kparA + ks * 16) * 2;
                ldm_x4(addrA, ah[mf][0], ah[mf][1], ah[mf][2], ah[mf][3]);
            }
            #pragma unroll
            for (int nf2 = 0; nf2 < 4; nf2++) {
                uint32_t bh[2][2];
                uint32_t addrB = bufb + OFF_B +
                    (uint32_t)(rowB + nf2 * 16) * 80 + (uint32_t)(kparB + ks * 16) * 2;
                ldm_x4(addrB, bh[0][0], bh[0][1], bh[1][0], bh[1][1]);
                #pragma unroll
                for (int mf = 0; mf < 4; mf++)
                    #pragma unroll
                    for (int j = 0; j < 2; j++)
                        mma_fp16(acc[mf][nf2 * 2 + j], ah[mf], bh[j]);
            }
        }
    }

    const int qrow = lane >> 2, qcol = (lane & 3) * 2;
    #pragma unroll
    for (int nf = 0; nf < 8; nf++) {
        const int col = col0 + wn * 64 + nf * 8 + qcol;
        #pragma unroll
        for (int mf = 0; mf < 4; mf++) {
            #pragma unroll
            for (int h = 0; h < 2; h++) {
                const int row = row0 + wm * 64 + mf * 16 + qrow + h * 8;
                float v0 = acc[mf][nf][h * 2 + 0];
                float v1 = acc[mf][nf][h * 2 + 1];
                *reinterpret_cast<__half2*>(C + (size_t)row * N + col) =
                    __halves2half2(__float2half(v0), __float2half(v1));
            }
        }
    }
}

// ============ HMMA split-K TN GEMM (1-pass) ==========
static constexpr int TK_PITCH = 272;
static constexpr int TK_PLANE = 32 * TK_PITCH;
static constexpr int TK_BUF   = 2 * TK_PLANE;
static constexpr int TK_SMEM  = 2 * TK_BUF;

__global__ __launch_bounds__(256, 1) void gemm_tn_mma(
    const __half* __restrict__ Ah, const __half* __restrict__ B,
    float* __restrict__ C, int Mc, int Nc, int Ktot, int kChunk, float scale) {
    extern __shared__ char smem[];
    const uint32_t sb = smem_u32(smem);
    const int tid = threadIdx.x, wid = tid >> 5, lane = tid & 31;
    const int col0 = blockIdx.x * 128;
    const int row0 = blockIdx.y * 128;
    const int n0 = blockIdx.z * kChunk;
    const int nEnd = min(n0 + kChunk, Ktot);
    const int wm = wid >> 2, wn = wid & 3;

    const __half* planes[2] = { Ah, B };
    const int baseCol[2] = { row0, col0 };
    const int strideK[2] = { Mc, Nc };

    const int lr0 = tid >> 4, lc0 = tid & 15;
    const int lr1 = lr0 + 16;

    auto load_chunk = [&](int i, int k0) {
        const uint32_t bufb = sb + (i & 1) * TK_BUF;
        #pragma unroll
        for (int p = 0; p < 2; p++) {
            const __half* src = planes[p];
            #pragma unroll
            for (int rep = 0; rep < 2; rep++) {
                int r = rep ? lr1 : lr0;
                int node = k0 + r;
                uint32_t sa = bufb + p * TK_PLANE + r * TK_PITCH + lc0 * 16;
                if (node < nEnd) {
                    CP_ASYNC16(sa, src + (size_t)node * strideK[p] + baseCol[p] + lc0 * 8);
                } else {
                    *reinterpret_cast<uint4*>(smem + (sa - sb)) = make_uint4(0, 0, 0, 0);
                }
            }
        }
        CP_COMMIT();
    };

    float acc[4][4][4];
    #pragma unroll
    for (int i = 0; i < 4; i++)
        #pragma unroll
        for (int j = 0; j < 4; j++)
            #pragma unroll
            for (int q = 0; q < 4; q++) acc[i][j][q] = 0.0f;

    const int krA = (lane & 7) + ((lane >> 4) << 3);
    const int mcA = ((lane >> 3) & 1) * 8;
    const int krB = (lane & 7) + (((lane >> 3) & 1) << 3);
    const int ncB = (lane >> 4) * 8;

    const int nCh = (nEnd - n0 + 31) >> 5;
    load_chunk(0, n0);

    for (int i = 0; i < nCh; i++) {
        const int k0 = n0 + i * 32;
        if (i + 1 < nCh) {
            load_chunk(i + 1, k0 + 32);
            asm volatile("cp.async.wait_group 1;");
        } else {
            asm volatile("cp.async.wait_group 0;");
        }
        __syncthreads();

        const uint32_t bufb = sb + (i & 1) * TK_BUF;
        #pragma unroll
        for (int ks = 0; ks < 2; ks++) {
            uint32_t bh[4][2];
            #pragma unroll
            for (int nf2 = 0; nf2 < 2; nf2++) {
                uint32_t aH = bufb + TK_PLANE +
                    (uint32_t)(krB + ks * 16) * TK_PITCH +
                    (uint32_t)(wn * 32 + nf2 * 16 + ncB) * 2;
                ldm_x4t(aH, bh[nf2 * 2][0], bh[nf2 * 2][1],
                            bh[nf2 * 2 + 1][0], bh[nf2 * 2 + 1][1]);
            }
            uint32_t ah[4][4];
            #pragma unroll
            for (int mf = 0; mf < 4; mf++) {
                uint32_t aH = bufb +
                    (uint32_t)(krA + ks * 16) * TK_PITCH +
                    (uint32_t)(wm * 64 + mf * 16 + mcA) * 2;
                ldm_x4t(aH, ah[mf][0], ah[mf][1], ah[mf][2], ah[mf][3]);
            }
            #pragma unroll
            for (int mf = 0; mf < 4; mf++)
                #pragma unroll
                for (int nf = 0; nf < 4; nf++)
                    mma_fp16(acc[mf][nf], ah[mf], bh[nf]);
        }
        __syncthreads();
    }

    const int qrow = lane >> 2, qcol = (lane & 3) * 2;
    #pragma unroll
    for (int mf = 0; mf < 4; mf++) {
        #pragma unroll
        for (int nf = 0; nf < 4; nf++) {
            #pragma unroll
            for (int h = 0; h < 2; h++) {
                const int row = row0 + wm * 64 + mf * 16 + qrow + h * 8;
                const int col = col0 + wn * 32 + nf * 8 + qcol;
                atomicAdd(&C[(size_t)row * Nc + col], acc[mf][nf][h * 2 + 0] * scale);
                atomicAdd(&C[(size_t)row * Nc + col + 1], acc[mf][nf][h * 2 + 1] * scale);
            }
        }
    }
}

// ---------------- fp32 -> fp16 converts ----------------
__global__ void convert4_kernel(
    const float* __restrict__ s0, __half* __restrict__ d0, int n0,
    const float* __restrict__ s1, __half* __restrict__ d1, int n1,
    const float* __restrict__ s2, __half* __restrict__ d2, int n2,
    const float* __restrict__ s3, __half* __restrict__ d3, int n3) {
    int i = blockIdx.x * 256 + threadIdx.x;
    if (i < n0) d0[i] = __float2half(s0[i]);
    i -= n0;
    if (i >= 0 && i < n1) d1[i] = __float2half(s1[i]);
    i -= n1;
    if (i >= 0 && i < n2) d2[i] = __float2half(s2[i]);
    i -= n2;
    if (i >= 0 && i < n3) d3[i] = __float2half(s3[i]);
}

// vectorized: 4 elems/thread (n must be divisible by 4)
__global__ void convert_v4_kernel(const float* __restrict__ src,
                                  __half* __restrict__ dst, int n4) {
    int i = blockIdx.x * 256 + threadIdx.x;
    if (i >= n4) return;
    float4 v = *reinterpret_cast<const float4*>(src + i * 4);
    __half2 lo = __halves2half2(__float2half(v.x), __float2half(v.y));
    __half2 hi = __halves2half2(__float2half(v.z), __float2half(v.w));
    *reinterpret_cast<__half2*>(dst + i * 4)     = lo;
    *reinterpret_cast<__half2*>(dst + i * 4 + 2) = hi;
}

// ---------------- K0: Zc ----------------
__global__ void zc_kernel(const float* __restrict__ Z,
                          const float* __restrict__ zcw,
                          const float* __restrict__ zcb,
                          __half* __restrict__ Zc, int NL) {
    int idx = blockIdx.x * 256 + threadIdx.x;
    if (idx >= NL) return;
    int n = idx >> 7, l = idx & 127;
    size_t base = (size_t)n * 384 + l;
    float z0 = Z[base], z1 = Z[base + 128], z2 = Z[base + 256];
    #pragma unroll
    for (int c = 0; c < 3; c++) {
        float v = zcw[c * 3 + 0] * z0 + zcw[c * 3 + 1] * z1 + zcw[c * 3 + 2] * z2 + zcb[c];
        Zc[base + (size_t)c * 128] = __float2half(v);
    }
}

// ---------------- K2: per-edge prep ----------------
__global__ __launch_bounds__(128) void edge_prep(
    const float* __restrict__ x, const float* __restrict__ Z,
    const int* __restrict__ tar,
    const float* __restrict__ zw1, const float* __restrict__ zb1,
    __half* __restrict__ Ph, __half* __restrict__ ZZh,
    __half* __restrict__ Gh, int E) {
    int e = blockIdx.x;
    int t = threadIdx.x;
    int src = tar[e], dst = tar[E + e];

    __shared__ float sZi[384], sZj[384];
    __shared__ float red[9][4];
    __shared__ float r9[9], rT9[9];

    const float* xs = x + (size_t)src * 256;
    const float* xd = x + (size_t)dst * 256;
    Ph[(size_t)e * 256 + t]       = __float2half(xs[t] * xd[t]);
    Ph[(size_t)e * 256 + t + 128] = __float2half(xs[t + 128] * xd[t + 128]);

    const float* Zi = Z + (size_t)src * 384;
    const float* Zj = Z + (size_t)dst * 384;
    for (int i = t; i < 384; i += 128) { sZi[i] = Zi[i]; sZj[i] = Zj[i]; }
    __syncthreads();

    for (int i = t; i < 384; i += 128)
        ZZh[(size_t)e * 384 + i] = __float2half(sZi[i] * sZj[i]);

    float loc[9];
    #pragma unroll
    for (int c = 0; c < 3; c++)
        #pragma unroll
        for (int d = 0; d < 3; d++)
            loc[c * 3 + d] = sZi[c * 128 + t] * sZj[d * 128 + t];
    #pragma unroll
    for (int off = 16; off > 0; off >>= 1)
        #pragma unroll
        for (int q = 0; q < 9; q++)
            loc[q] += __shfl_down_sync(0xffffffffu, loc[q], off);
    int warp = t >> 5, lane = t & 31;
    if (lane == 0)
        #pragma unroll
        for (int q = 0; q < 9; q++) red[q][warp] = loc[q];
    __syncthreads();
    if (t < 9) r9[t] = (red[t][0] + red[t][1] + red[t][2] + red[t][3]) * (1.0f / 128.0f);
    __syncthreads();
    if (t < 9) { int c = t / 3, d = t % 3; rT9[t] = r9[d * 3 + c]; }
    __syncthreads();

    #pragma unroll
    for (int rep = 0; rep < 2; rep++) {
        int o = t + rep * 128;
        const float* w = zw1 + (size_t)o * 9;
        float s1 = zb1[o], s2 = zb1[o];
        #pragma unroll
        for (int q = 0; q < 9; q++) { s1 += r9[q] * w[q]; s2 += rT9[q] * w[q]; }
        Gh[(size_t)e * 256 + o]       = __float2half(silu_f(s1));
        Gh[(size_t)(E + e) * 256 + o] = __float2half(silu_f(s2));
    }
}

// ---------------- K4: 4 LayerNorms + product + final dot ----------------
__global__ __launch_bounds__(256) void final_kernel(
    const __half* __restrict__ XIJ, const __half* __restrict__ U,
    const __half* __restrict__ XZX,
    const float* __restrict__ xg, const float* __restrict__ xb,
    const float* __restrict__ zg, const float* __restrict__ zb,
    const float* __restrict__ zxg, const float* __restrict__ zxb,
    const float* __restrict__ lw, const float* __restrict__ lb,
    float* __restrict__ out, int E) {
    int e = blockIdx.x;
    int t = threadIdx.x;
    const __half2* pxij = reinterpret_cast<const __half2*>(XIJ + (size_t)e * 768);
    const __half2* pu1  = reinterpret_cast<const __half2*>(U   + (size_t)e * 768);
    const __half2* pu2  = reinterpret_cast<const __half2*>(U   + (size_t)(E + e) * 768);
    const __half2* pxzx = reinterpret_cast<const __half2*>(XZX + (size_t)e * 768);

    __shared__ float red[8][8];
    __shared__ float stats[8];
    __shared__ float dred[8];

    float v0[4], v1[4], v2[4], v3[4];
    float s[8];
    #pragma unroll
    for (int q = 0; q < 8; q++) s[q] = 0.0f;
    #pragma unroll
    for (int j = 0; j < 2; j++) {
        if (j == 0 || t < 128) {
            int idx = t + j * 256;
            float2 a = __half22float2(pxij[idx]);
            float2 b = __half22float2(pu1[idx]);
            float2 c = __half22float2(pu2[idx]);
            float2 d = __half22float2(pxzx[idx]);
            v0[j*2] = a.x; v0[j*2+1] = a.y;
            v1[j*2] = b.x; v1[j*2+1] = b.y;
            v2[j*2] = c.x; v2[j*2+1] = c.y;
            v3[j*2] = d.x; v3[j*2+1] = d.y;
            s[0] += a.x + a.y; s[1] += a.x*a.x + a.y*a.y;
            s[2] += b.x + b.y; s[3] += b.x*b.x + b.y*b.y;
            s[4] += c.x + c.y; s[5] += c.x*c.x + c.y*c.y;
            s[6] += d.x + d.y; s[7] += d.x*d.x + d.y*d.y;
        }
    }
    #pragma unroll
    for (int off = 16; off > 0; off >>= 1)
        #pragma unroll
        for (int q = 0; q < 8; q++)
            s[q] += __shfl_down_sync(0xffffffffu, s[q], off);
    int warp = t >> 5, lane = t & 31;
    if (lane == 0)
        #pragma unroll
        for (int q = 0; q < 8; q++) red[q][warp] = s[q];
    __syncthreads();
    if (t < 8) {
        float tot = 0.0f;
        #pragma unroll
        for (int w = 0; w < 8; w++) tot += red[t][w];
        stats[t] = tot;
    }
    __syncthreads();

    const float inv = 1.0f / 768.0f;
    const float eps = 1e-5f;
    float m0 = stats[0] * inv, r0 = rsqrtf(stats[1] * inv - m0 * m0 + eps);
    float m1 = stats[2] * inv, r1 = rsqrtf(stats[3] * inv - m1 * m1 + eps);
    float m2 = stats[4] * inv, r2 = rsqrtf(stats[5] * inv - m2 * m2 + eps);
    float m3 = stats[6] * inv, r3 = rsqrtf(stats[7] * inv - m3 * m3 + eps);

    float dot = 0.0f;
    #pragma unroll
    for (int j = 0; j < 2; j++) {
        if (j == 0 || t < 128) {
            int idx = t + j * 256;
            float2 gx  = *reinterpret_cast<const float2*>(xg  + idx * 2);
            float2 bx  = *reinterpret_cast<const float2*>(xb  + idx * 2);
            float2 gz  = *reinterpret_cast<const float2*>(zg  + idx * 2);
            float2 bz  = *reinterpret_cast<const float2*>(zb  + idx * 2);
            float2 gzx = *reinterpret_cast<const float2*>(zxg + idx * 2);
            float2 bzx = *reinterpret_cast<const float2*>(zxb + idx * 2);
            float2 wl  = *reinterpret_cast<const float2*>(lw  + idx * 2);
            #pragma unroll
            for (int h = 0; h < 2; h++) {
                float ga = h ? gx.y : gx.x,  ba = h ? bx.y : bx.x;
                float gb = h ? gz.y : gz.x,  bb = h ? bz.y : bz.x;
                float gc = h ? gzx.y : gzx.x, bc = h ? bzx.y : bzx.x;
                float wv = h ? wl.y : wl.x;
                float a  = (v0[j*2+h] - m0) * r0 * ga + ba;
                float b1 = (v1[j*2+h] - m1) * r1 * gb + bb;
                float b2 = (v2[j*2+h] - m2) * r2 * gb + bb;
                float c  = (v3[j*2+h] - m3) * r3 * gc + bc;
                dot += a * (b1 + b2) * c * wv;
            }
        }
    }
    #pragma unroll
    for (int off = 16; off > 0; off >>= 1)
        dot += __shfl_down_sync(0xffffffffu, dot, off);
    if (lane == 0) dred[warp] = dot;
    __syncthreads();
    if (t == 0) {
        float tot = 0.0f;
        #pragma unroll
        for (int w = 0; w < 8; w++) tot += dred[w];
        out[e] = tot + lb[0];
    }
}

// ---------------- launch ----------------
extern "C" void kernel_launch(void* const* d_in, const int* in_sizes, int n_in,
                              void* d_out, int out_size) {
    const float* x   = (const float*)d_in[0];
    const float* Z   = (const float*)d_in[1];
    const int*   tar = (const int*)  d_in[3];
    const float* xij_w1 = (const float*)d_in[4];
    const float* xij_b1 = (const float*)d_in[5];
    const float* xij_w2 = (const float*)d_in[6];
    const float* xij_b2 = (const float*)d_in[7];
    const float* xij_ln_g = (const float*)d_in[8];
    const float* xij_ln_b = (const float*)d_in[9];
    const float* z_w1 = (const float*)d_in[10];
    const float* z_b1 = (const float*)d_in[11];
    const float* z_w2 = (const float*)d_in[12];
    const float* z_b2 = (const float*)d_in[13];
    const float* z_ln_g = (const float*)d_in[14];
    const float* z_ln_b = (const float*)d_in[15];
    const float* zc_w = (const float*)d_in[16];
    const float* zc_b = (const float*)d_in[17];
    const float* zx_w = (const float*)d_in[18];
    const float* zx_b = (const float*)d_in[19];
    const float* zx_ln_g = (const float*)d_in[20];
    const float* zx_ln_b = (const float*)d_in[21];
    const float* lin_w = (const float*)d_in[22];
    const float* lin_b = (const float*)d_in[23];

    int N = in_sizes[0] / 256;
    int E = in_sizes[3] / 2;
    float zx_coeff = (float)(1.0 / (sqrt((double)N) * 3840.0));

    float* ZXT;
    cudaGetSymbolAddress((void**)&ZXT, g_ZXT);
    __half *XIJ, *U, *XZX;
    cudaGetSymbolAddress((void**)&XIJ, g_XIJ);
    cudaGetSymbolAddress((void**)&U,   g_U);
    cudaGetSymbolAddress((void**)&XZX, g_XZX);

    __half *xh,*Zc,*Ph,*ZZh,*Gh,*Hh,*Th;
    __half *W1,*W2,*ZW2,*ZXW,*ZXTq;
    cudaGetSymbolAddress((void**)&xh,  g_xh);
    cudaGetSymbolAddress((void**)&Zc,  g_Zc);
    cudaGetSymbolAddress((void**)&Ph,  g_Ph);
    cudaGetSymbolAddress((void**)&ZZh, g_ZZh);
    cudaGetSymbolAddress((void**)&Gh,  g_Gh);
    cudaGetSymbolAddress((void**)&Hh,  g_Hh);
    cudaGetSymbolAddress((void**)&Th,  g_Th);
    cudaGetSymbolAddress((void**)&W1,  g_W1);  cudaGetSymbolAddress((void**)&W2,  g_W2);
    cudaGetSymbolAddress((void**)&ZW2, g_ZW2); cudaGetSymbolAddress((void**)&ZXW, g_ZXW);
    cudaGetSymbolAddress((void**)&ZXTq,g_ZXTq);

    cudaFuncSetAttribute(gemm_panel<true >, cudaFuncAttributeMaxDynamicSharedMemorySize, PG_SMEM);
    cudaFuncSetAttribute(gemm_panel<false>, cudaFuncAttributeMaxDynamicSharedMemorySize, PG_SMEM);
    cudaFuncSetAttribute(gemm_mma_t, cudaFuncAttributeMaxDynamicSharedMemorySize, GEMM_SMEM);
    cudaFuncSetAttribute(gemm_tn_mma, cudaFuncAttributeMaxDynamicSharedMemorySize, TK_SMEM);

    // weight converts (merged)
    convert4_kernel<<<(655360 + 255) / 256, 256>>>(
        xij_w1, W1, 65536, xij_w2, W2, 196608,
        z_w2, ZW2, 196608, zx_w, ZXW, 196608);

    // edge prep + biggest GEMM early
    edge_prep<<<E, 128>>>(x, Z, tar, z_w1, z_b1, Ph, ZZh, Gh, E);
    gemm_panel<true ><<<2 * E / 128, 256, PG_SMEM>>>(Gh, ZW2, z_b2, U, 2 * E, 768);

    // zx node path
    int NL = N * 128;
    convert_v4_kernel<<<(N * 64 + 255) / 256, 256>>>(x, xh, N * 64);
    zc_kernel<<<(NL + 255) / 256, 256>>>(Z, zc_w, zc_b, Zc, NL);
    cudaMemsetAsync(ZXT, 0, 256 * 384 * sizeof(float), 0);
    {
        int kChunk = 4000;
        int splits = (N + kChunk - 1) / kChunk;
        dim3 grid(3, 2, splits);
        gemm_tn_mma<<<grid, 256, TK_SMEM>>>(xh, Zc, ZXT, 256, 384, N, kChunk, zx_coeff);
    }
    convert_v4_kernel<<<(24576 + 255) / 256, 256>>>(ZXT, ZXTq, 24576);

    // separate panel GEMMs (R13 structure — fused version spilled & regressed)
    gemm_panel<true ><<<E / 128, 256, PG_SMEM>>>(Ph, W1, xij_b1, Hh, E, 256);
    gemm_panel<false><<<E / 128, 256, PG_SMEM>>>(Hh, W2, xij_b2, XIJ, E, 768);
    {
        dim3 gT(2, E / 256);
        gemm_mma_t<<<gT, 256, GEMM_SMEM>>>(ZZh, ZXTq, Th, E, 256, 384);
    }
    gemm_panel<false><<<E / 128, 256, PG_SMEM>>>(Th, ZXW, zx_b, XZX, E, 768);

    final_kernel<<<E, 256>>>(XIJ, U, XZX,
                             xij_ln_g, xij_ln_b, z_ln_g, z_ln_b,
                             zx_ln_g, zx_ln_b, lin_w, lin_b,
                             (float*)d_out, E);
}

// round 16
// speedup vs baseline: 1.5281x; 1.5006x over previous
#include <cuda_runtime.h>
#include <cuda_fp16.h>
#include <math.h>
#include <stdint.h>

#define MAXN 100000
#define MAXE 131072

// ---------------- scratch (device globals; no allocation allowed) ----------------
__device__ __align__(128) float  g_ZXT[256 * 384];
__device__ __align__(128) __half g_XIJ[(size_t)MAXE * 768];
__device__ __align__(128) __half g_U[(size_t)2 * MAXE * 768];   // U1 | U2
__device__ __align__(128) __half g_XZX[(size_t)MAXE * 768];

// fp16 planes
__device__ __align__(128) __half g_xh [(size_t)MAXN * 256];
__device__ __align__(128) __half g_Zc [(size_t)MAXN * 384];
__device__ __align__(128) __half g_Ph [(size_t)MAXE * 256];
__device__ __align__(128) __half g_ZZh[(size_t)MAXE * 384];
__device__ __align__(128) __half g_Gh [(size_t)2 * MAXE * 256]; // G1|G2
__device__ __align__(128) __half g_Hh [(size_t)MAXE * 256];
__device__ __align__(128) __half g_Th [(size_t)MAXE * 256];
// weights, single fp16 plane
__device__ __align__(128) __half g_W1 [256 * 256];
__device__ __align__(128) __half g_W2 [768 * 256];
__device__ __align__(128) __half g_ZW2[768 * 256];
__device__ __align__(128) __half g_ZXW[768 * 256];
__device__ __align__(128) __half g_ZXTq[256 * 384];

__device__ __forceinline__ float silu_f(float v) { return v / (1.0f + __expf(-v)); }

__device__ __forceinline__ uint32_t smem_u32(const void* p) {
    uint32_t a;
    asm("{ .reg .u64 t; cvta.to.shared.u64 t, %1; cvt.u32.u64 %0, t; }" : "=r"(a) : "l"(p));
    return a;
}

#define CP_ASYNC16(saddr, gptr) \
    asm volatile("cp.async.cg.shared.global [%0], [%1], 16;" :: "r"(saddr), "l"(gptr))
#define CP_COMMIT() asm volatile("cp.async.commit_group;")

__device__ __forceinline__ void ldm_x4(uint32_t addr, uint32_t& r0, uint32_t& r1,
                                       uint32_t& r2, uint32_t& r3) {
    asm volatile("ldmatrix.sync.aligned.m8n8.x4.shared.b16 {%0,%1,%2,%3}, [%4];"
                 : "=r"(r0), "=r"(r1), "=r"(r2), "=r"(r3) : "r"(addr));
}
__device__ __forceinline__ void ldm_x4t(uint32_t addr, uint32_t& r0, uint32_t& r1,
                                        uint32_t& r2, uint32_t& r3) {
    asm volatile("ldmatrix.sync.aligned.m8n8.x4.trans.shared.b16 {%0,%1,%2,%3}, [%4];"
                 : "=r"(r0), "=r"(r1), "=r"(r2), "=r"(r3) : "r"(addr));
}
__device__ __forceinline__ void mma_fp16(float* c, const uint32_t* a, const uint32_t* b) {
    asm volatile(
        "mma.sync.aligned.m16n8k16.row.col.f32.f16.f16.f32 "
        "{%0,%1,%2,%3}, {%4,%5,%6,%7}, {%8,%9}, {%0,%1,%2,%3};"
        : "+f"(c[0]), "+f"(c[1]), "+f"(c[2]), "+f"(c[3])
        : "r"(a[0]), "r"(a[1]), "r"(a[2]), "r"(a[3]), "r"(b[0]), "r"(b[1]));
}

static constexpr int P_PITCH = 528;                 // 256 fp16 + 16B pad
static constexpr int A_PANEL = 128 * P_PITCH;       // 67584
static constexpr int PG_SMEM = 3 * A_PANEL;         // 202752

// ===== Panel GEMM (K=256): A panel resident in SMEM, loop over N col-blocks =====
template <bool SILU>
__global__ __launch_bounds__(256, 1) void gemm_panel(
    const __half* __restrict__ A, const __half* __restrict__ B,
    const float* __restrict__ bias,
    __half* __restrict__ C,
    int M, int N) {
    const int K = 256;
    extern __shared__ char smem[];
    const uint32_t sb = smem_u32(smem);
    const int tid = threadIdx.x, wid = tid >> 5, lane = tid & 31;
    const int row0 = blockIdx.x * 128;
    const int wm = wid & 3, wn = wid >> 2;
    const int NB = N >> 7;

    auto load_A = [&]() {
        #pragma unroll
        for (int it = 0; it < 16; it++) {
            int idx = tid + it * 256;
            int r = idx >> 5, c = idx & 31;
            CP_ASYNC16(sb + r * P_PITCH + c * 16,
                       A + (size_t)(row0 + r) * K + c * 8);
        }
        CP_COMMIT();
    };
    auto load_B = [&](int j) {
        const uint32_t bb = sb + A_PANEL + (j & 1) * A_PANEL;
        const int cb = j * 128;
        #pragma unroll
        for (int it = 0; it < 16; it++) {
            int idx = tid + it * 256;
            int r = idx >> 5, c = idx & 31;
            CP_ASYNC16(bb + r * P_PITCH + c * 16,
                       B + (size_t)(cb + r) * K + c * 8);
        }
        CP_COMMIT();
    };

    load_A();
    load_B(0);
    asm volatile("cp.async.wait_group 0;");
    __syncthreads();

    const int rowA = wm * 32 + (lane & 15);
    const int kparA = (lane >> 4) * 8;
    const int rowB = (lane & 7) + ((lane >> 4) << 3);
    const int kparB = ((lane >> 3) & 1) * 8;
    const int qrow = lane >> 2, qcol = (lane & 3) * 2;

    for (int j = 0; j < NB; j++) {
        if (j + 1 < NB) load_B(j + 1);

        float acc[2][8][4];
        #pragma unroll
        for (int i = 0; i < 2; i++)
            #pragma unroll
            for (int q = 0; q < 8; q++)
                #pragma unroll
                for (int h = 0; h < 4; h++) acc[i][q][h] = 0.0f;

        const uint32_t bb = sb + A_PANEL + (j & 1) * A_PANEL;
        #pragma unroll
        for (int ks = 0; ks < 16; ks++) {
            uint32_t ah[2][4];
            #pragma unroll
            for (int mf = 0; mf < 2; mf++) {
                uint32_t aA = sb + (uint32_t)(rowA + mf * 16) * P_PITCH +
                              (uint32_t)(kparA + ks * 16) * 2;
                ldm_x4(aA, ah[mf][0], ah[mf][1], ah[mf][2], ah[mf][3]);
            }
            #pragma unroll
            for (int nf2 = 0; nf2 < 4; nf2++) {
                uint32_t bh[2][2];
                uint32_t aB = bb + (uint32_t)(wn * 64 + nf2 * 16 + rowB) * P_PITCH +
                              (uint32_t)(kparB + ks * 16) * 2;
                ldm_x4(aB, bh[0][0], bh[0][1], bh[1][0], bh[1][1]);
                #pragma unroll
                for (int mf = 0; mf < 2; mf++)
                    #pragma unroll
                    for (int q = 0; q < 2; q++)
                        mma_fp16(acc[mf][nf2 * 2 + q], ah[mf], bh[q]);
            }
        }

        #pragma unroll
        for (int nf = 0; nf < 8; nf++) {
            const int col = j * 128 + wn * 64 + nf * 8 + qcol;
            float b0 = bias ? bias[col] : 0.0f;
            float b1 = bias ? bias[col + 1] : 0.0f;
            #pragma unroll
            for (int mf = 0; mf < 2; mf++) {
                #pragma unroll
                for (int h = 0; h < 2; h++) {
                    const int row = row0 + wm * 32 + mf * 16 + qrow + h * 8;
                    float v0 = acc[mf][nf][h * 2 + 0] + b0;
                    float v1 = acc[mf][nf][h * 2 + 1] + b1;
                    if (SILU) { v0 = silu_f(v0); v1 = silu_f(v1); }
                    *reinterpret_cast<__half2*>(C + (size_t)row * N + col) =
                        __halves2half2(__float2half(v0), __float2half(v1));
                }
            }
        }

        if (j + 1 < NB) {
            asm volatile("cp.async.wait_group 0;");
            __syncthreads();
        }
    }
}

// ===== streaming HMMA GEMM for T (K=384) =====
static constexpr int OFF_B = 20480;
static constexpr int BUF   = 30720;
static constexpr int GEMM_SMEM = 3 * BUF;

__global__ __launch_bounds__(256, 1) void gemm_mma_t(
    const __half* __restrict__ A, const __half* __restrict__ B,
    __half* __restrict__ C,
    int M, int N, int K) {
    extern __shared__ char smem[];
    const uint32_t sb = smem_u32(smem);
    const int tid = threadIdx.x, wid = tid >> 5, lane = tid & 31;
    const int col0 = blockIdx.x * 128;
    const int row0 = blockIdx.y * 256;
    const int wm = wid & 3, wn = wid >> 2;

    const int ldr = tid >> 2, ldc = tid & 3;

    auto load_chunk = [&](int i) {
        const uint32_t bufb = sb + (i % 3) * BUF;
        const int k0 = i * 32;
        #pragma unroll
        for (int g = 0; g < 4; g++) {
            int r = ldr + g * 64;
            CP_ASYNC16(bufb + r * 80 + ldc * 16,
                       A + (size_t)(row0 + r) * K + k0 + ldc * 8);
        }
        #pragma unroll
        for (int g = 0; g < 2; g++) {
            int r = ldr + g * 64;
            CP_ASYNC16(bufb + OFF_B + r * 80 + ldc * 16,
                       B + (size_t)(col0 + r) * K + k0 + ldc * 8);
        }
        CP_COMMIT();
    };

    float acc[4][8][4];
    #pragma unroll
    for (int i = 0; i < 4; i++)
        #pragma unroll
        for (int j = 0; j < 8; j++)
            #pragma unroll
            for (int q = 0; q < 4; q++) acc[i][j][q] = 0.0f;

    const int rowA = wm * 64 + (lane & 15);
    const int kparA = (lane >> 4) * 8;
    const int rowB = wn * 64 + (lane & 7) + ((lane >> 4) << 3);
    const int kparB = ((lane >> 3) & 1) * 8;

    const int nCh = K >> 5;
    load_chunk(0);
    if (nCh > 1) load_chunk(1);

    for (int i = 0; i < nCh; i++) {
        if (i + 1 < nCh) {
            asm volatile("cp.async.wait_group 1;");
        } else {
            asm volatile("cp.async.wait_group 0;");
        }
        __syncthreads();
        if (i + 2 < nCh) load_chunk(i + 2);

        const uint32_t bufb = sb + (i % 3) * BUF;
        #pragma unroll
        for (int ks = 0; ks < 2; ks++) {
            uint32_t ah[4][4];
            #pragma unroll
            for (int mf = 0; mf < 4; mf++) {
                uint32_t addrA = bufb +
                    (uint32_t)(rowA + mf * 16) * 80 + (uint32_t)(kparA + ks * 16) * 2;
                ldm_x4(addrA, ah[mf][0], ah[mf][1], ah[mf][2], ah[mf][3]);
            }
            #pragma unroll
            for (int nf2 = 0; nf2 < 4; nf2++) {
                uint32_t bh[2][2];
                uint32_t addrB = bufb + OFF_B +
                    (uint32_t)(rowB + nf2 * 16) * 80 + (uint32_t)(kparB + ks * 16) * 2;
                ldm_x4(addrB, bh[0][0], bh[0][1], bh[1][0], bh[1][1]);
                #pragma unroll
                for (int mf = 0; mf < 4; mf++)
                    #pragma unroll
                    for (int j = 0; j < 2; j++)
                        mma_fp16(acc[mf][nf2 * 2 + j], ah[mf], bh[j]);
            }
        }
    }

    const int qrow = lane >> 2, qcol = (lane & 3) * 2;
    #pragma unroll
    for (int nf = 0; nf < 8; nf++) {
        const int col = col0 + wn * 64 + nf * 8 + qcol;
        #pragma unroll
        for (int mf = 0; mf < 4; mf++) {
            #pragma unroll
            for (int h = 0; h < 2; h++) {
                const int row = row0 + wm * 64 + mf * 16 + qrow + h * 8;
                float v0 = acc[mf][nf][h * 2 + 0];
                float v1 = acc[mf][nf][h * 2 + 1];
                *reinterpret_cast<__half2*>(C + (size_t)row * N + col) =
                    __halves2half2(__float2half(v0), __float2half(v1));
            }
        }
    }
}

// ============ HMMA split-K TN GEMM (1-pass) ==========
static constexpr int TK_PITCH = 272;
static constexpr int TK_PLANE = 32 * TK_PITCH;
static constexpr int TK_BUF   = 2 * TK_PLANE;
static constexpr int TK_SMEM  = 2 * TK_BUF;

__global__ __launch_bounds__(256, 1) void gemm_tn_mma(
    const __half* __restrict__ Ah, const __half* __restrict__ B,
    float* __restrict__ C, int Mc, int Nc, int Ktot, int kChunk, float scale) {
    extern __shared__ char smem[];
    const uint32_t sb = smem_u32(smem);
    const int tid = threadIdx.x, wid = tid >> 5, lane = tid & 31;
    const int col0 = blockIdx.x * 128;
    const int row0 = blockIdx.y * 128;
    const int n0 = blockIdx.z * kChunk;
    const int nEnd = min(n0 + kChunk, Ktot);
    const int wm = wid >> 2, wn = wid & 3;

    const __half* planes[2] = { Ah, B };
    const int baseCol[2] = { row0, col0 };
    const int strideK[2] = { Mc, Nc };

    const int lr0 = tid >> 4, lc0 = tid & 15;
    const int lr1 = lr0 + 16;

    auto load_chunk = [&](int i, int k0) {
        const uint32_t bufb = sb + (i & 1) * TK_BUF;
        #pragma unroll
        for (int p = 0; p < 2; p++) {
            const __half* src = planes[p];
            #pragma unroll
            for (int rep = 0; rep < 2; rep++) {
                int r = rep ? lr1 : lr0;
                int node = k0 + r;
                uint32_t sa = bufb + p * TK_PLANE + r * TK_PITCH + lc0 * 16;
                if (node < nEnd) {
                    CP_ASYNC16(sa, src + (size_t)node * strideK[p] + baseCol[p] + lc0 * 8);
                } else {
                    *reinterpret_cast<uint4*>(smem + (sa - sb)) = make_uint4(0, 0, 0, 0);
                }
            }
        }
        CP_COMMIT();
    };

    float acc[4][4][4];
    #pragma unroll
    for (int i = 0; i < 4; i++)
        #pragma unroll
        for (int j = 0; j < 4; j++)
            #pragma unroll
            for (int q = 0; q < 4; q++) acc[i][j][q] = 0.0f;

    const int krA = (lane & 7) + ((lane >> 4) << 3);
    const int mcA = ((lane >> 3) & 1) * 8;
    const int krB = (lane & 7) + (((lane >> 3) & 1) << 3);
    const int ncB = (lane >> 4) * 8;

    const int nCh = (nEnd - n0 + 31) >> 5;
    load_chunk(0, n0);

    for (int i = 0; i < nCh; i++) {
        const int k0 = n0 + i * 32;
        if (i + 1 < nCh) {
            load_chunk(i + 1, k0 + 32);
            asm volatile("cp.async.wait_group 1;");
        } else {
            asm volatile("cp.async.wait_group 0;");
        }
        __syncthreads();

        const uint32_t bufb = sb + (i & 1) * TK_BUF;
        #pragma unroll
        for (int ks = 0; ks < 2; ks++) {
            uint32_t bh[4][2];
            #pragma unroll
            for (int nf2 = 0; nf2 < 2; nf2++) {
                uint32_t aH = bufb + TK_PLANE +
                    (uint32_t)(krB + ks * 16) * TK_PITCH +
                    (uint32_t)(wn * 32 + nf2 * 16 + ncB) * 2;
                ldm_x4t(aH, bh[nf2 * 2][0], bh[nf2 * 2][1],
                            bh[nf2 * 2 + 1][0], bh[nf2 * 2 + 1][1]);
            }
            uint32_t ah[4][4];
            #pragma unroll
            for (int mf = 0; mf < 4; mf++) {
                uint32_t aH = bufb +
                    (uint32_t)(krA + ks * 16) * TK_PITCH +
                    (uint32_t)(wm * 64 + mf * 16 + mcA) * 2;
                ldm_x4t(aH, ah[mf][0], ah[mf][1], ah[mf][2], ah[mf][3]);
            }
            #pragma unroll
            for (int mf = 0; mf < 4; mf++)
                #pragma unroll
                for (int nf = 0; nf < 4; nf++)
                    mma_fp16(acc[mf][nf], ah[mf], bh[nf]);
        }
        __syncthreads();
    }

    const int qrow = lane >> 2, qcol = (lane & 3) * 2;
    #pragma unroll
    for (int mf = 0; mf < 4; mf++) {
        #pragma unroll
        for (int nf = 0; nf < 4; nf++) {
            #pragma unroll
            for (int h = 0; h < 2; h++) {
                const int row = row0 + wm * 64 + mf * 16 + qrow + h * 8;
                const int col = col0 + wn * 32 + nf * 8 + qcol;
                atomicAdd(&C[(size_t)row * Nc + col], acc[mf][nf][h * 2 + 0] * scale);
                atomicAdd(&C[(size_t)row * Nc + col + 1], acc[mf][nf][h * 2 + 1] * scale);
            }
        }
    }
}

// ---------------- fp32 -> fp16 converts ----------------
__global__ void convert4_kernel(
    const float* __restrict__ s0, __half* __restrict__ d0, int n0,
    const float* __restrict__ s1, __half* __restrict__ d1, int n1,
    const float* __restrict__ s2, __half* __restrict__ d2, int n2,
    const float* __restrict__ s3, __half* __restrict__ d3, int n3) {
    int i = blockIdx.x * 256 + threadIdx.x;
    if (i < n0) d0[i] = __float2half(s0[i]);
    i -= n0;
    if (i >= 0 && i < n1) d1[i] = __float2half(s1[i]);
    i -= n1;
    if (i >= 0 && i < n2) d2[i] = __float2half(s2[i]);
    i -= n2;
    if (i >= 0 && i < n3) d3[i] = __float2half(s3[i]);
}

// vectorized: 4 elems/thread
__global__ void convert_v4_kernel(const float* __restrict__ src,
                                  __half* __restrict__ dst, int n4) {
    int i = blockIdx.x * 256 + threadIdx.x;
    if (i >= n4) return;
    float4 v = *reinterpret_cast<const float4*>(src + i * 4);
    __half2 lo = __halves2half2(__float2half(v.x), __float2half(v.y));
    __half2 hi = __halves2half2(__float2half(v.z), __float2half(v.w));
    *reinterpret_cast<__half2*>(dst + i * 4)     = lo;
    *reinterpret_cast<__half2*>(dst + i * 4 + 2) = hi;
}

// ---------------- K0: Zc (vectorized: 4 L-positions per thread) ----------------
__global__ void zc_kernel(const float* __restrict__ Z,
                          const float* __restrict__ zcw,
                          const float* __restrict__ zcb,
                          __half* __restrict__ Zc, int Nq) {   // Nq = N*32
    int idx = blockIdx.x * 256 + threadIdx.x;
    if (idx >= Nq) return;
    int n = idx >> 5, l4 = (idx & 31) * 4;
    size_t base = (size_t)n * 384 + l4;
    float4 z0 = *reinterpret_cast<const float4*>(Z + base);
    float4 z1 = *reinterpret_cast<const float4*>(Z + base + 128);
    float4 z2 = *reinterpret_cast<const float4*>(Z + base + 256);
    #pragma unroll
    for (int c = 0; c < 3; c++) {
        float w0 = zcw[c * 3 + 0], w1 = zcw[c * 3 + 1], w2 = zcw[c * 3 + 2], b = zcb[c];
        float v0 = w0 * z0.x + w1 * z1.x + w2 * z2.x + b;
        float v1 = w0 * z0.y + w1 * z1.y + w2 * z2.y + b;
        float v2 = w0 * z0.z + w1 * z1.z + w2 * z2.z + b;
        float v3 = w0 * z0.w + w1 * z1.w + w2 * z2.w + b;
        __half* dst = Zc + base + (size_t)c * 128;
        *reinterpret_cast<__half2*>(dst)     = __halves2half2(__float2half(v0), __float2half(v1));
        *reinterpret_cast<__half2*>(dst + 2) = __halves2half2(__float2half(v2), __float2half(v3));
    }
}

// ---------------- K2: per-edge prep (float2-vectorized x path) ----------------
__global__ __launch_bounds__(128) void edge_prep(
    const float* __restrict__ x, const float* __restrict__ Z,
    const int* __restrict__ tar,
    const float* __restrict__ zw1, const float* __restrict__ zb1,
    __half* __restrict__ Ph, __half* __restrict__ ZZh,
    __half* __restrict__ Gh, int E) {
    int e = blockIdx.x;
    int t = threadIdx.x;
    int src = tar[e], dst = tar[E + e];

    __shared__ float sZi[384], sZj[384];
    __shared__ float red[9][4];
    __shared__ float r9[9], rT9[9];

    // P = xi*xj, vectorized: thread t handles elems 2t, 2t+1
    {
        const float2* xs = reinterpret_cast<const float2*>(x + (size_t)src * 256);
        const float2* xd = reinterpret_cast<const float2*>(x + (size_t)dst * 256);
        float2 a = xs[t], b = xd[t];
        *reinterpret_cast<__half2*>(Ph + (size_t)e * 256 + t * 2) =
            __halves2half2(__float2half(a.x * b.x), __float2half(a.y * b.y));
    }

    const float* Zi = Z + (size_t)src * 384;
    const float* Zj = Z + (size_t)dst * 384;
    for (int i = t; i < 384; i += 128) { sZi[i] = Zi[i]; sZj[i] = Zj[i]; }
    __syncthreads();

    for (int i = t; i < 384; i += 128)
        ZZh[(size_t)e * 384 + i] = __float2half(sZi[i] * sZj[i]);

    float loc[9];
    #pragma unroll
    for (int c = 0; c < 3; c++)
        #pragma unroll
        for (int d = 0; d < 3; d++)
            loc[c * 3 + d] = sZi[c * 128 + t] * sZj[d * 128 + t];
    #pragma unroll
    for (int off = 16; off > 0; off >>= 1)
        #pragma unroll
        for (int q = 0; q < 9; q++)
            loc[q] += __shfl_down_sync(0xffffffffu, loc[q], off);
    int warp = t >> 5, lane = t & 31;
    if (lane == 0)
        #pragma unroll
        for (int q = 0; q < 9; q++) red[q][warp] = loc[q];
    __syncthreads();
    if (t < 9) r9[t] = (red[t][0] + red[t][1] + red[t][2] + red[t][3]) * (1.0f / 128.0f);
    __syncthreads();
    if (t < 9) { int c = t / 3, d = t % 3; rT9[t] = r9[d * 3 + c]; }
    __syncthreads();

    #pragma unroll
    for (int rep = 0; rep < 2; rep++) {
        int o = t + rep * 128;
        const float* w = zw1 + (size_t)o * 9;
        float s1 = zb1[o], s2 = zb1[o];
        #pragma unroll
        for (int q = 0; q < 9; q++) { s1 += r9[q] * w[q]; s2 += rT9[q] * w[q]; }
        Gh[(size_t)e * 256 + o]       = __float2half(silu_f(s1));
        Gh[(size_t)(E + e) * 256 + o] = __float2half(silu_f(s2));
    }
}

// ---------------- K4: 4 LayerNorms + product + final dot ----------------
__global__ __launch_bounds__(256) void final_kernel(
    const __half* __restrict__ XIJ, const __half* __restrict__ U,
    const __half* __restrict__ XZX,
    const float* __restrict__ xg, const float* __restrict__ xb,
    const float* __restrict__ zg, const float* __restrict__ zb,
    const float* __restrict__ zxg, const float* __restrict__ zxb,
    const float* __restrict__ lw, const float* __restrict__ lb,
    float* __restrict__ out, int E) {
    int e = blockIdx.x;
    int t = threadIdx.x;
    const __half2* pxij = reinterpret_cast<const __half2*>(XIJ + (size_t)e * 768);
    const __half2* pu1  = reinterpret_cast<const __half2*>(U   + (size_t)e * 768);
    const __half2* pu2  = reinterpret_cast<const __half2*>(U   + (size_t)(E + e) * 768);
    const __half2* pxzx = reinterpret_cast<const __half2*>(XZX + (size_t)e * 768);

    __shared__ float red[8][8];
    __shared__ float stats[8];
    __shared__ float dred[8];

    float v0[4], v1[4], v2[4], v3[4];
    float s[8];
    #pragma unroll
    for (int q = 0; q < 8; q++) s[q] = 0.0f;
    #pragma unroll
    for (int j = 0; j < 2; j++) {
        if (j == 0 || t < 128) {
            int idx = t + j * 256;
            float2 a = __half22float2(pxij[idx]);
            float2 b = __half22float2(pu1[idx]);
            float2 c = __half22float2(pu2[idx]);
            float2 d = __half22float2(pxzx[idx]);
            v0[j*2] = a.x; v0[j*2+1] = a.y;
            v1[j*2] = b.x; v1[j*2+1] = b.y;
            v2[j*2] = c.x; v2[j*2+1] = c.y;
            v3[j*2] = d.x; v3[j*2+1] = d.y;
            s[0] += a.x + a.y; s[1] += a.x*a.x + a.y*a.y;
            s[2] += b.x + b.y; s[3] += b.x*b.x + b.y*b.y;
            s[4] += c.x + c.y; s[5] += c.x*c.x + c.y*c.y;
            s[6] += d.x + d.y; s[7] += d.x*d.x + d.y*d.y;
        }
    }
    #pragma unroll
    for (int off = 16; off > 0; off >>= 1)
        #pragma unroll
        for (int q = 0; q < 8; q++)
            s[q] += __shfl_down_sync(0xffffffffu, s[q], off);
    int warp = t >> 5, lane = t & 31;
    if (lane == 0)
        #pragma unroll
        for (int q = 0; q < 8; q++) red[q][warp] = s[q];
    __syncthreads();
    if (t < 8) {
        float tot = 0.0f;
        #pragma unroll
        for (int w = 0; w < 8; w++) tot += red[t][w];
        stats[t] = tot;
    }
    __syncthreads();

    const float inv = 1.0f / 768.0f;
    const float eps = 1e-5f;
    float m0 = stats[0] * inv, r0 = rsqrtf(stats[1] * inv - m0 * m0 + eps);
    float m1 = stats[2] * inv, r1 = rsqrtf(stats[3] * inv - m1 * m1 + eps);
    float m2 = stats[4] * inv, r2 = rsqrtf(stats[5] * inv - m2 * m2 + eps);
    float m3 = stats[6] * inv, r3 = rsqrtf(stats[7] * inv - m3 * m3 + eps);

    float dot = 0.0f;
    #pragma unroll
    for (int j = 0; j < 2; j++) {
        if (j == 0 || t < 128) {
            int idx = t + j * 256;
            float2 gx  = *reinterpret_cast<const float2*>(xg  + idx * 2);
            float2 bx  = *reinterpret_cast<const float2*>(xb  + idx * 2);
            float2 gz  = *reinterpret_cast<const float2*>(zg  + idx * 2);
            float2 bz  = *reinterpret_cast<const float2*>(zb  + idx * 2);
            float2 gzx = *reinterpret_cast<const float2*>(zxg + idx * 2);
            float2 bzx = *reinterpret_cast<const float2*>(zxb + idx * 2);
            float2 wl  = *reinterpret_cast<const float2*>(lw  + idx * 2);
            #pragma unroll
            for (int h = 0; h < 2; h++) {
                float ga = h ? gx.y : gx.x,  ba = h ? bx.y : bx.x;
                float gb = h ? gz.y : gz.x,  bb = h ? bz.y : bz.x;
                float gc = h ? gzx.y : gzx.x, bc = h ? bzx.y : bzx.x;
                float wv = h ? wl.y : wl.x;
                float a  = (v0[j*2+h] - m0) * r0 * ga + ba;
                float b1 = (v1[j*2+h] - m1) * r1 * gb + bb;
                float b2 = (v2[j*2+h] - m2) * r2 * gb + bb;
                float c  = (v3[j*2+h] - m3) * r3 * gc + bc;
                dot += a * (b1 + b2) * c * wv;
            }
        }
    }
    #pragma unroll
    for (int off = 16; off > 0; off >>= 1)
        dot += __shfl_down_sync(0xffffffffu, dot, off);
    if (lane == 0) dred[warp] = dot;
    __syncthreads();
    if (t == 0) {
        float tot = 0.0f;
        #pragma unroll
        for (int w = 0; w < 8; w++) tot += dred[w];
        out[e] = tot + lb[0];
    }
}

// ---------------- launch ----------------
extern "C" void kernel_launch(void* const* d_in, const int* in_sizes, int n_in,
                              void* d_out, int out_size) {
    const float* x   = (const float*)d_in[0];
    const float* Z   = (const float*)d_in[1];
    const int*   tar = (const int*)  d_in[3];
    const float* xij_w1 = (const float*)d_in[4];
    const float* xij_b1 = (const float*)d_in[5];
    const float* xij_w2 = (const float*)d_in[6];
    const float* xij_b2 = (const float*)d_in[7];
    const float* xij_ln_g = (const float*)d_in[8];
    const float* xij_ln_b = (const float*)d_in[9];
    const float* z_w1 = (const float*)d_in[10];
    const float* z_b1 = (const float*)d_in[11];
    const float* z_w2 = (const float*)d_in[12];
    const float* z_b2 = (const float*)d_in[13];
    const float* z_ln_g = (const float*)d_in[14];
    const float* z_ln_b = (const float*)d_in[15];
    const float* zc_w = (const float*)d_in[16];
    const float* zc_b = (const float*)d_in[17];
    const float* zx_w = (const float*)d_in[18];
    const float* zx_b = (const float*)d_in[19];
    const float* zx_ln_g = (const float*)d_in[20];
    const float* zx_ln_b = (const float*)d_in[21];
    const float* lin_w = (const float*)d_in[22];
    const float* lin_b = (const float*)d_in[23];

    int N = in_sizes[0] / 256;
    int E = in_sizes[3] / 2;
    float zx_coeff = (float)(1.0 / (sqrt((double)N) * 3840.0));

    float* ZXT;
    cudaGetSymbolAddress((void**)&ZXT, g_ZXT);
    __half *XIJ, *U, *XZX;
    cudaGetSymbolAddress((void**)&XIJ, g_XIJ);
    cudaGetSymbolAddress((void**)&U,   g_U);
    cudaGetSymbolAddress((void**)&XZX, g_XZX);

    __half *xh,*Zc,*Ph,*ZZh,*Gh,*Hh,*Th;
    __half *W1,*W2,*ZW2,*ZXW,*ZXTq;
    cudaGetSymbolAddress((void**)&xh,  g_xh);
    cudaGetSymbolAddress((void**)&Zc,  g_Zc);
    cudaGetSymbolAddress((void**)&Ph,  g_Ph);
    cudaGetSymbolAddress((void**)&ZZh, g_ZZh);
    cudaGetSymbolAddress((void**)&Gh,  g_Gh);
    cudaGetSymbolAddress((void**)&Hh,  g_Hh);
    cudaGetSymbolAddress((void**)&Th,  g_Th);
    cudaGetSymbolAddress((void**)&W1,  g_W1);  cudaGetSymbolAddress((void**)&W2,  g_W2);
    cudaGetSymbolAddress((void**)&ZW2, g_ZW2); cudaGetSymbolAddress((void**)&ZXW, g_ZXW);
    cudaGetSymbolAddress((void**)&ZXTq,g_ZXTq);

    cudaFuncSetAttribute(gemm_panel<true >, cudaFuncAttributeMaxDynamicSharedMemorySize, PG_SMEM);
    cudaFuncSetAttribute(gemm_panel<false>, cudaFuncAttributeMaxDynamicSharedMemorySize, PG_SMEM);
    cudaFuncSetAttribute(gemm_mma_t, cudaFuncAttributeMaxDynamicSharedMemorySize, GEMM_SMEM);
    cudaFuncSetAttribute(gemm_tn_mma, cudaFuncAttributeMaxDynamicSharedMemorySize, TK_SMEM);

    // weight converts (merged)
    convert4_kernel<<<(655360 + 255) / 256, 256>>>(
        xij_w1, W1, 65536, xij_w2, W2, 196608,
        z_w2, ZW2, 196608, zx_w, ZXW, 196608);

    // edge prep + biggest GEMM early
    edge_prep<<<E, 128>>>(x, Z, tar, z_w1, z_b1, Ph, ZZh, Gh, E);
    gemm_panel<true ><<<2 * E / 128, 256, PG_SMEM>>>(Gh, ZW2, z_b2, U, 2 * E, 768);

    // zx node path
    convert_v4_kernel<<<(N * 64 + 255) / 256, 256>>>(x, xh, N * 64);
    zc_kernel<<<(N * 32 + 255) / 256, 256>>>(Z, zc_w, zc_b, Zc, N * 32);
    cudaMemsetAsync(ZXT, 0, 256 * 384 * sizeof(float), 0);
    {
        int kChunk = 4000;
        int splits = (N + kChunk - 1) / kChunk;
        dim3 grid(3, 2, splits);
        gemm_tn_mma<<<grid, 256, TK_SMEM>>>(xh, Zc, ZXT, 256, 384, N, kChunk, zx_coeff);
    }
    convert_v4_kernel<<<(24576 + 255) / 256, 256>>>(ZXT, ZXTq, 24576);

    // edge GEMMs (proven-fast panel structure)
    gemm_panel<true ><<<E / 128, 256, PG_SMEM>>>(Ph, W1, xij_b1, Hh, E, 256);
    gemm_panel<false><<<E / 128, 256, PG_SMEM>>>(Hh, W2, xij_b2, XIJ, E, 768);
    {
        dim3 gT(2, E / 256);
        gemm_mma_t<<<gT, 256, GEMM_SMEM>>>(ZZh, ZXTq, Th, E, 256, 384);
    }
    gemm_panel<false><<<E / 128, 256, PG_SMEM>>>(Th, ZXW, zx_b, XZX, E, 768);

    final_kernel<<<E, 256>>>(XIJ, U, XZX,
                             xij_ln_g, xij_ln_b, z_ln_g, z_ln_b,
                             zx_ln_g, zx_ln_b, lin_w, lin_b,
                             (float*)d_out, E);
}